// round 12
// baseline (speedup 1.0000x reference)
#include <cuda_runtime.h>
#include <cuda_fp16.h>
#include <math.h>
#include <stdint.h>

#define CCH 512
#define NPX 4096
typedef __half fp16;

static const size_t NH  = (size_t)NPX * CCH;
static const size_t NN  = (size_t)NPX * NPX;
static const size_t NQK = (size_t)NPX * 1024;
#define WS ((size_t)CCH * CCH)

// ---------------- static scratch ----------------
__device__ fp16  g_ht[(size_t)2 * NPX * CCH];    // GN output [B][N][C]
__device__ fp16  g_w[(size_t)4 * CCH * CCH];     // wq,wk,wv,wp fp16
__device__ fp16  g_wvT[(size_t)CCH * CCH];       // wv^T fp16
__device__ fp16  g_wpv[(size_t)CCH * CCH];       // Wpv = wp@wv fp16
__device__ float g_bpv[CCH];                     // wp@bv
__device__ float g_bqk[1024];                    // concat bq|bk
__device__ fp16  g_qk[(size_t)2 * NPX * 1024];   // [B][N][1024]: Q|K
__device__ fp16  g_wv16[(size_t)2 * CCH * NPX];  // WpV [B][C][N]
__device__ fp16  g_E[(size_t)2 * NPX * NPX];     // exp(scores) fp16
__device__ float g_part[(size_t)2 * NPX * 16];   // per-(row, nblock) partial sums

// ---------------- helpers ----------------
__device__ __forceinline__ uint32_t smem_u32(const void* p) {
    uint32_t a;
    asm("{ .reg .u64 t; cvta.to.shared.u64 t, %1; cvt.u32.u64 %0, t; }" : "=r"(a) : "l"(p));
    return a;
}
__device__ __forceinline__ uint32_t pack2(fp16 a, fp16 b) {
    __half2 t; t.x = a; t.y = b;
    return *reinterpret_cast<uint32_t*>(&t);
}
__device__ __forceinline__ void cp16(uint32_t s, const void* g) {
    asm volatile("cp.async.cg.shared.global [%0], [%1], 16;" :: "r"(s), "l"(g));
}
__device__ __forceinline__ void ldsm4(uint32_t* r, uint32_t addr) {
    asm volatile("ldmatrix.sync.aligned.m8n8.x4.shared.b16 {%0,%1,%2,%3}, [%4];"
        : "=r"(r[0]), "=r"(r[1]), "=r"(r[2]), "=r"(r[3]) : "r"(addr));
}
__device__ __forceinline__ void mma16816(float* d, const uint32_t* a, uint32_t b0, uint32_t b1) {
    asm volatile("mma.sync.aligned.m16n8k16.row.col.f32.f16.f16.f32 "
        "{%0,%1,%2,%3}, {%4,%5,%6,%7}, {%8,%9}, {%0,%1,%2,%3};"
        : "+f"(d[0]), "+f"(d[1]), "+f"(d[2]), "+f"(d[3])
        : "r"(a[0]), "r"(a[1]), "r"(a[2]), "r"(a[3]), "r"(b0), "r"(b1));
}

// ---------------- fused prep: wconv + wvT + bqk + bpv + GroupNorm ----------------
// blocks [0,4096): elementwise fp16 convert of wq|wk|wv|wp
// blocks [4096,4352): 32x32 transpose tiles of wv (fp32 -> fp16 wvT)
// blocks [4352,4356): bqk concat
// blocks [4356,4420): bpv = wp@bv, warp per channel
// blocks [4420,4484): GroupNorm (one per (b,g))
__global__ void __launch_bounds__(256) prep_all(const float* __restrict__ wq,
                                                const float* __restrict__ wk,
                                                const float* __restrict__ wv,
                                                const float* __restrict__ wp,
                                                const float* __restrict__ bq,
                                                const float* __restrict__ bk,
                                                const float* __restrict__ bv,
                                                const float* __restrict__ x,
                                                const float* __restrict__ gamma,
                                                const float* __restrict__ beta) {
    int bid = blockIdx.x;
    int tid = threadIdx.x;
    if (bid < 4096) {
        size_t i = (size_t)bid * 256 + tid;
        size_t which = i / WS, r = i - which * WS;
        const float* w = (which == 0) ? wq : (which == 1) ? wk : (which == 2) ? wv : wp;
        g_w[i] = __float2half(w[r]);
        return;
    }
    if (bid < 4352) {
        int t = bid - 4096;
        int bx = (t & 15) * 32, by = (t >> 4) * 32;
        int tx = tid & 31, ty = tid >> 5;    // 32 x 8
        __shared__ fp16 sm[32][33];
        #pragma unroll
        for (int r = 0; r < 32; r += 8)
            sm[ty + r][tx] = __float2half(wv[(size_t)(by + ty + r) * CCH + bx + tx]);
        __syncthreads();
        #pragma unroll
        for (int r = 0; r < 32; r += 8)
            g_wvT[(size_t)(bx + ty + r) * CCH + by + tx] = sm[tx][ty + r];
        return;
    }
    if (bid < 4356) {
        int i = (bid - 4352) * 256 + tid;
        g_bqk[i] = (i < 512) ? bq[i] : bk[i - 512];
        return;
    }
    if (bid < 4420) {
        int wid = tid >> 5, lane = tid & 31;
        int c = (bid - 4356) * 8 + wid;
        const float* row = wp + (size_t)c * CCH;
        float s = 0.f;
        #pragma unroll
        for (int j = 0; j < 16; j++) s += row[lane + j * 32] * bv[lane + j * 32];
        #pragma unroll
        for (int o = 16; o > 0; o >>= 1) s += __shfl_xor_sync(0xffffffffu, s, o);
        if (lane == 0) g_bpv[c] = s;
        return;
    }
    // ---- GroupNorm branch ----
    {
        int gb = bid - 4420;
        int b = gb >> 5;
        int g = gb & 31;
        const size_t base = ((size_t)b * CCH + (size_t)g * 16) * NPX;
        const float4* xp = (const float4*)(x + base);
        const int TOT4 = 16 * NPX / 4;

        float s = 0.f, ss = 0.f;
        for (int i = tid; i < TOT4; i += 256) {
            float4 v = xp[i];
            s  += v.x + v.y + v.z + v.w;
            ss += v.x * v.x + v.y * v.y + v.z * v.z + v.w * v.w;
        }
        __shared__ float rs[8], rss[8];
        #pragma unroll
        for (int o = 16; o > 0; o >>= 1) {
            s  += __shfl_xor_sync(0xffffffffu, s, o);
            ss += __shfl_xor_sync(0xffffffffu, ss, o);
        }
        if ((tid & 31) == 0) { rs[tid >> 5] = s; rss[tid >> 5] = ss; }
        __syncthreads();
        float S = 0.f, SS = 0.f;
        #pragma unroll
        for (int w = 0; w < 8; w++) { S += rs[w]; SS += rss[w]; }
        const float inv_cnt = 1.0f / (float)(16 * NPX);
        float mean = S * inv_cnt;
        float var  = SS * inv_cnt - mean * mean;
        float rstd = rsqrtf(var + 1e-6f);

        __shared__ float sga[16], sbe[16];
        if (tid < 16) {
            int c = g * 16 + tid;
            float ga = gamma[c] * rstd;
            sga[tid] = ga;
            sbe[tid] = beta[c] - mean * ga;
        }
        __shared__ float xs[16][256];
        __syncthreads();

        for (int p0 = 0; p0 < NPX; p0 += 256) {
            #pragma unroll
            for (int c = 0; c < 16; c++) xs[c][tid] = x[base + (size_t)c * NPX + p0 + tid];
            __syncthreads();
            uint32_t hw[8];
            #pragma unroll
            for (int c2 = 0; c2 < 8; c2++) {
                float v0 = xs[2 * c2][tid]     * sga[2 * c2]     + sbe[2 * c2];
                float v1 = xs[2 * c2 + 1][tid] * sga[2 * c2 + 1] + sbe[2 * c2 + 1];
                hw[c2] = pack2(__float2half(v0), __float2half(v1));
            }
            size_t o = ((size_t)b * NPX + p0 + tid) * CCH + g * 16;
            ((uint4*)(g_ht + o))[0] = make_uint4(hw[0], hw[1], hw[2], hw[3]);
            ((uint4*)(g_ht + o))[1] = make_uint4(hw[4], hw[5], hw[6], hw[7]);
            __syncthreads();
        }
    }
}

// ---------------- small GEMM: Wpv = wp @ wv  (512x512x512), CTA 64x64, grid 8x8 ----------------
#define SROWB 144
#define SSTG_A (64 * SROWB)        // 9216
#define SSTG   (2 * SSTG_A)        // 18432
__global__ void __launch_bounds__(256) wpv_gemm(const fp16* __restrict__ A,   // wp [512,512]
                                                const fp16* __restrict__ B,   // wvT [512,512]
                                                fp16* __restrict__ D) {
    extern __shared__ char smemraw[];
    int tid = threadIdx.x, wid = tid >> 5, lane = tid & 31;
    int m0 = blockIdx.y * 64, n0 = blockIdx.x * 64;
    uint32_t base = smem_u32(smemraw);
    int wm = wid & 1, wn = wid >> 1;   // 2 x 4 warps; warp tile 32(m) x 16(n)

    float acc[2][2][4];
    #pragma unroll
    for (int a = 0; a < 2; a++)
        #pragma unroll
        for (int b = 0; b < 2; b++)
            #pragma unroll
            for (int c = 0; c < 4; c++) acc[a][b][c] = 0.f;

    auto load_chunk = [&](int i) {
        int st = i % 3;
        size_t kb = (size_t)i * 64;
        uint32_t sa = base + st * SSTG;
        uint32_t sb = sa + SSTG_A;
        #pragma unroll
        for (int r = 0; r < 2; r++) {
            int u = tid + r * 256;       // 0..511
            int row = u >> 3, cs = u & 7;
            cp16(sa + (uint32_t)(row * SROWB + cs * 16),
                 A + (size_t)(m0 + row) * CCH + kb + cs * 8);
            cp16(sb + (uint32_t)(row * SROWB + cs * 16),
                 B + (size_t)(n0 + row) * CCH + kb + cs * 8);
        }
    };

    load_chunk(0);
    asm volatile("cp.async.commit_group;" ::: "memory");
    load_chunk(1);
    asm volatile("cp.async.commit_group;" ::: "memory");

    uint32_t a_off[2], b_off;
    #pragma unroll
    for (int mi = 0; mi < 2; mi++) {
        int row = wm * 32 + mi * 16 + (lane & 15);
        a_off[mi] = (uint32_t)(row * SROWB + ((lane >> 4) * 8) * 2);
    }
    {
        int row = wn * 16 + ((lane >> 4) << 3) + (lane & 7);
        b_off = (uint32_t)(row * SROWB + ((((lane >> 3) & 1) << 3)) * 2);
    }

    const int nch = 8;                  // K = 512
    for (int i = 0; i < nch; i++) {
        if (i < nch - 1) asm volatile("cp.async.wait_group 1;" ::: "memory");
        else             asm volatile("cp.async.wait_group 0;" ::: "memory");
        __syncthreads();
        if (i + 2 < nch) {
            load_chunk(i + 2);
            asm volatile("cp.async.commit_group;" ::: "memory");
        }
        uint32_t sa = base + (i % 3) * SSTG;
        uint32_t sb = sa + SSTG_A;

        #pragma unroll
        for (int kk = 0; kk < 4; kk++) {
            uint32_t ko = (uint32_t)(kk * 32);
            uint32_t afr[2][4], bfr[4];
            #pragma unroll
            for (int mi = 0; mi < 2; mi++) ldsm4(afr[mi], sa + a_off[mi] + ko);
            ldsm4(bfr, sb + b_off + ko);
            #pragma unroll
            for (int mi = 0; mi < 2; mi++)
                #pragma unroll
                for (int ni = 0; ni < 2; ni++)
                    mma16816(acc[mi][ni], afr[mi], bfr[ni * 2], bfr[ni * 2 + 1]);
        }
        __syncthreads();
    }

    int r4 = lane >> 2;
    int c2 = lane & 3;
    #pragma unroll
    for (int mi = 0; mi < 2; mi++)
        #pragma unroll
        for (int half = 0; half < 2; half++) {
            int m = m0 + wm * 32 + mi * 16 + half * 8 + r4;
            #pragma unroll
            for (int ni = 0; ni < 2; ni++) {
                int n = n0 + wn * 16 + ni * 8 + c2 * 2;
                *(uint32_t*)(D + (size_t)m * CCH + n) =
                    pack2(__float2half(acc[mi][ni][half * 2 + 0]),
                          __float2half(acc[mi][ni][half * 2 + 1]));
            }
        }
}

// ================= f32-acc GEMM: CTA 128x256, warp 64x64, BK=64, 3-stage =================
#define ROWB  144
#define STG_A (128 * ROWB)
#define STG_B (256 * ROWB)
#define STG   (STG_A + STG_B)

#define GEMM_MAINLOOP() \
    uint32_t base = smem_u32(smemraw); \
    int wm = wid & 1, wn = wid >> 1; \
    const int nch = K >> 6; \
    float acc[4][8][4]; \
    _Pragma("unroll") \
    for (int a_ = 0; a_ < 4; a_++) \
        _Pragma("unroll") \
        for (int b_ = 0; b_ < 8; b_++) \
            _Pragma("unroll") \
            for (int c_ = 0; c_ < 4; c_++) acc[a_][b_][c_] = 0.f; \
    auto load_chunk = [&](int i) { \
        int st = i % 3; \
        size_t kb = (size_t)i * 64; \
        uint32_t sa = base + st * STG; \
        uint32_t sb = sa + STG_A; \
        _Pragma("unroll") \
        for (int r = 0; r < 4; r++) { \
            int u = tid + r * 256; \
            int row = u >> 3, cs = u & 7; \
            cp16(sa + (uint32_t)(row * ROWB + cs * 16), \
                 A + (size_t)(m0 + row) * ldA + kb + cs * 8); \
        } \
        _Pragma("unroll") \
        for (int r = 0; r < 8; r++) { \
            int u = tid + r * 256; \
            int row = u >> 3, cs = u & 7; \
            cp16(sb + (uint32_t)(row * ROWB + cs * 16), \
                 B + (size_t)(n0 + row) * ldB + kb + cs * 8); \
        } \
    }; \
    load_chunk(0); \
    asm volatile("cp.async.commit_group;" ::: "memory"); \
    if (nch > 1) load_chunk(1); \
    asm volatile("cp.async.commit_group;" ::: "memory"); \
    uint32_t a_off[4], b_off[4]; \
    _Pragma("unroll") \
    for (int mi = 0; mi < 4; mi++) { \
        int row = wm * 64 + mi * 16 + (lane & 15); \
        a_off[mi] = (uint32_t)(row * ROWB + ((lane >> 4) * 8) * 2); \
    } \
    _Pragma("unroll") \
    for (int nb = 0; nb < 4; nb++) { \
        int row = wn * 64 + nb * 16 + ((lane >> 4) << 3) + (lane & 7); \
        b_off[nb] = (uint32_t)(row * ROWB + ((((lane >> 3) & 1) << 3)) * 2); \
    } \
    for (int i = 0; i < nch; i++) { \
        if (i < nch - 1) asm volatile("cp.async.wait_group 1;" ::: "memory"); \
        else             asm volatile("cp.async.wait_group 0;" ::: "memory"); \
        __syncthreads(); \
        if (i + 2 < nch) { \
            load_chunk(i + 2); \
            asm volatile("cp.async.commit_group;" ::: "memory"); \
        } \
        uint32_t sa = base + (i % 3) * STG; \
        uint32_t sb = sa + STG_A; \
        uint32_t afr[2][4][4], bfr[2][4][4]; \
        _Pragma("unroll") \
        for (int mi = 0; mi < 4; mi++) ldsm4(afr[0][mi], sa + a_off[mi]); \
        _Pragma("unroll") \
        for (int nb = 0; nb < 4; nb++) ldsm4(bfr[0][nb], sb + b_off[nb]); \
        _Pragma("unroll") \
        for (int kk = 0; kk < 4; kk++) { \
            int cur = kk & 1, nxt = cur ^ 1; \
            if (kk < 3) { \
                uint32_t ko = (uint32_t)((kk + 1) * 32); \
                _Pragma("unroll") \
                for (int mi = 0; mi < 4; mi++) ldsm4(afr[nxt][mi], sa + a_off[mi] + ko); \
                _Pragma("unroll") \
                for (int nb = 0; nb < 4; nb++) ldsm4(bfr[nxt][nb], sb + b_off[nb] + ko); \
            } \
            _Pragma("unroll") \
            for (int mi = 0; mi < 4; mi++) \
                _Pragma("unroll") \
                for (int ni = 0; ni < 8; ni++) \
                    mma16816(acc[mi][ni], afr[cur][mi], \
                             bfr[cur][ni >> 1][(ni & 1) * 2], bfr[cur][ni >> 1][(ni & 1) * 2 + 1]); \
        } \
    }

// ---- general GEMM (fp16 out, biasRow/biasCol) ----
__global__ void gemm_hmma(
    const fp16* __restrict__ A, int ldA, size_t strideA,
    const fp16* __restrict__ B, int ldB, size_t strideB,
    int K,
    fp16* __restrict__ outH,
    int ldD, size_t strideD,
    const float* __restrict__ biasRow,
    const float* __restrict__ biasCol)
{
    extern __shared__ char smemraw[];
    int tid = threadIdx.x, wid = tid >> 5, lane = tid & 31;
    int m0 = blockIdx.y * 128, n0 = blockIdx.x * 256, bz = blockIdx.z;
    A += (size_t)bz * strideA;
    B += (size_t)bz * strideB;

    GEMM_MAINLOOP()

    int r4 = lane >> 2;
    int c2 = lane & 3;
    fp16* oh = outH + (size_t)bz * strideD;

    #pragma unroll
    for (int mi = 0; mi < 4; mi++) {
        #pragma unroll
        for (int half = 0; half < 2; half++) {
            int m = m0 + wm * 64 + mi * 16 + half * 8 + r4;
            float brow = biasRow ? biasRow[m] : 0.f;
            #pragma unroll
            for (int ni = 0; ni < 8; ni++) {
                int n = n0 + wn * 64 + ni * 8 + c2 * 2;
                float v0 = acc[mi][ni][half * 2 + 0] + brow;
                float v1 = acc[mi][ni][half * 2 + 1] + brow;
                if (biasCol) { v0 += biasCol[n]; v1 += biasCol[n + 1]; }
                *(uint32_t*)(oh + (size_t)m * ldD + n) = pack2(__float2half(v0), __float2half(v1));
            }
        }
    }
}

// ---- scores GEMM: E=exp(scale*s) fp16 + per-row partial sums ----
__global__ void gemm_scores(
    const fp16* __restrict__ A, int ldA, size_t strideA,
    const fp16* __restrict__ B, int ldB, size_t strideB,
    int K,
    fp16* __restrict__ outE, int ldD, size_t strideD,
    float scale)
{
    extern __shared__ char smemraw[];
    int tid = threadIdx.x, wid = tid >> 5, lane = tid & 31;
    int m0 = blockIdx.y * 128, n0 = blockIdx.x * 256, bz = blockIdx.z;
    A += (size_t)bz * strideA;
    B += (size_t)bz * strideB;

    GEMM_MAINLOOP()

    int r4 = lane >> 2;
    int c2 = lane & 3;
    fp16* oh = outE + (size_t)bz * strideD;
    float rsum[8];
    #pragma unroll
    for (int r = 0; r < 8; r++) rsum[r] = 0.f;

    #pragma unroll
    for (int mi = 0; mi < 4; mi++) {
        #pragma unroll
        for (int half = 0; half < 2; half++) {
            int m = m0 + wm * 64 + mi * 16 + half * 8 + r4;
            float rs = 0.f;
            #pragma unroll
            for (int ni = 0; ni < 8; ni++) {
                int n = n0 + wn * 64 + ni * 8 + c2 * 2;
                float e0 = __expf(acc[mi][ni][half * 2 + 0] * scale);
                float e1 = __expf(acc[mi][ni][half * 2 + 1] * scale);
                *(uint32_t*)(oh + (size_t)m * ldD + n) = pack2(__float2half(e0), __float2half(e1));
                rs += e0 + e1;
            }
            rsum[mi * 2 + half] = rs;
        }
    }
    #pragma unroll
    for (int r = 0; r < 8; r++) {
        rsum[r] += __shfl_xor_sync(0xffffffffu, rsum[r], 1);
        rsum[r] += __shfl_xor_sync(0xffffffffu, rsum[r], 2);
    }
    __syncthreads();
    float* sp = (float*)smemraw;
    if (c2 == 0) {
        #pragma unroll
        for (int mi = 0; mi < 4; mi++)
            #pragma unroll
            for (int half = 0; half < 2; half++) {
                int rl = wm * 64 + mi * 16 + half * 8 + r4;
                sp[rl * 4 + wn] = rsum[mi * 2 + half];
            }
    }
    __syncthreads();
    if (tid < 128) {
        float s = sp[tid * 4] + sp[tid * 4 + 1] + sp[tid * 4 + 2] + sp[tid * 4 + 3];
        g_part[((size_t)bz * NPX + m0 + tid) * 16 + blockIdx.x] = s;
    }
}

// ---- final GEMM: out = (WpV @ E^T) * inv_rowsum + biasRow + resid ----
__global__ void gemm_final(
    const fp16* __restrict__ A, int ldA, size_t strideA,
    const fp16* __restrict__ B, int ldB, size_t strideB,
    int K,
    float* __restrict__ outF32, int ldD, size_t strideD,
    const float* __restrict__ biasRow,
    const float* __restrict__ resid)
{
    extern __shared__ char smemraw[];
    int tid = threadIdx.x, wid = tid >> 5, lane = tid & 31;
    int m0 = blockIdx.y * 128, n0 = blockIdx.x * 256, bz = blockIdx.z;
    A += (size_t)bz * strideA;
    B += (size_t)bz * strideB;

    GEMM_MAINLOOP()

    // inverse row sums for this CTA's 256 columns
    float* sp = (float*)smemraw;
    {
        const float* p = g_part + ((size_t)bz * NPX + n0 + tid) * 16;
        float s = 0.f;
        #pragma unroll
        for (int k = 0; k < 16; k++) s += p[k];
        sp[tid] = 1.0f / s;
    }
    __syncthreads();

    int r4 = lane >> 2;
    int c2 = lane & 3;
    float* of = outF32 + (size_t)bz * strideD;
    const float* rp = resid + (size_t)bz * strideD;

    #pragma unroll
    for (int mi = 0; mi < 4; mi++) {
        #pragma unroll
        for (int half = 0; half < 2; half++) {
            int m = m0 + wm * 64 + mi * 16 + half * 8 + r4;
            float brow = biasRow[m];
            #pragma unroll
            for (int ni = 0; ni < 8; ni++) {
                int n = n0 + wn * 64 + ni * 8 + c2 * 2;
                float v0 = acc[mi][ni][half * 2 + 0] * sp[n - n0]     + brow;
                float v1 = acc[mi][ni][half * 2 + 1] * sp[n + 1 - n0] + brow;
                size_t off = (size_t)m * ldD + n;
                float2 q = *(const float2*)(rp + off);
                v0 += q.x; v1 += q.y;
                *(float2*)(of + off) = make_float2(v0, v1);
            }
        }
    }
}

// ---------------- launch ----------------
extern "C" void kernel_launch(void* const* d_in, const int* in_sizes, int n_in,
                              void* d_out, int out_size) {
    const float* x     = (const float*)d_in[0];
    const float* gamma = (const float*)d_in[1];
    const float* beta  = (const float*)d_in[2];
    const float* wq    = (const float*)d_in[3];
    const float* bq    = (const float*)d_in[4];
    const float* wk    = (const float*)d_in[5];
    const float* bk    = (const float*)d_in[6];
    const float* wv    = (const float*)d_in[7];
    const float* bv    = (const float*)d_in[8];
    const float* wp    = (const float*)d_in[9];
    const float* bp    = (const float*)d_in[10];
    float* out = (float*)d_out;

    fp16 *ht, *w, *wvT, *wpv, *qk, *wv16, *E;
    float *bqk, *bpv;
    cudaGetSymbolAddress((void**)&ht, g_ht);
    cudaGetSymbolAddress((void**)&w, g_w);
    cudaGetSymbolAddress((void**)&wvT, g_wvT);
    cudaGetSymbolAddress((void**)&wpv, g_wpv);
    cudaGetSymbolAddress((void**)&qk, g_qk);
    cudaGetSymbolAddress((void**)&wv16, g_wv16);
    cudaGetSymbolAddress((void**)&E, g_E);
    cudaGetSymbolAddress((void**)&bqk, g_bqk);
    cudaGetSymbolAddress((void**)&bpv, g_bpv);

    const int SMEM_DYN = 3 * STG;      // 162 KB
    const int SMEM_WPV = 3 * SSTG;     // 55 KB
    cudaFuncSetAttribute(gemm_hmma, cudaFuncAttributeMaxDynamicSharedMemorySize, SMEM_DYN);
    cudaFuncSetAttribute(gemm_scores, cudaFuncAttributeMaxDynamicSharedMemorySize, SMEM_DYN);
    cudaFuncSetAttribute(gemm_final, cudaFuncAttributeMaxDynamicSharedMemorySize, SMEM_DYN);
    cudaFuncSetAttribute(wpv_gemm, cudaFuncAttributeMaxDynamicSharedMemorySize, SMEM_WPV);

    // fused prep + groupnorm
    prep_all<<<4484, 256>>>(wq, wk, wv, wp, bq, bk, bv, x, gamma, beta);

    // Wpv = wp @ wv : [512,512] fp16, small-tile GEMM across 64 CTAs
    wpv_gemm<<<dim3(8, 8, 1), 256, SMEM_WPV>>>(w + 3 * WS, wvT, wpv);

    // QK: D[4096,1024] = ht @ [wq;wk]^T + bqk -> fp16
    gemm_hmma<<<dim3(1024 / 256, NPX / 128, 2), 256, SMEM_DYN>>>(
        ht, CCH, NH, w, CCH, 0, CCH,
        qk, 1024, NQK, nullptr, bqk);

    // WpV = Wpv @ ht^T + bpv : [512,4096] fp16
    gemm_hmma<<<dim3(NPX / 256, CCH / 128, 2), 256, SMEM_DYN>>>(
        wpv, CCH, 0, ht, CCH, NH, CCH,
        wv16, NPX, NH, bpv, nullptr);

    // scores -> E = exp(scale * Q@K^T) fp16 + partial sums
    const float scale = 1.0f / sqrtf((float)CCH);
    gemm_scores<<<dim3(NPX / 256, NPX / 128, 2), 256, SMEM_DYN>>>(
        qk, 1024, NQK, qk + 512, 1024, NQK, CCH,
        E, NPX, NN, scale);

    // final: out[c,i] = (sum_j WpV[c,j]*E[i,j]) * invs[i] + bp[c] + x[c,i]
    gemm_final<<<dim3(NPX / 256, CCH / 128, 2), 256, SMEM_DYN>>>(
        wv16, NPX, NH, E, NPX, NN, NPX,
        out, NPX, (size_t)CCH * NPX, bp, x);
}

// round 13
// speedup vs baseline: 1.0691x; 1.0691x over previous
#include <cuda_runtime.h>
#include <cuda_fp16.h>
#include <math.h>
#include <stdint.h>

#define CCH 512
#define NPX 4096
typedef __half fp16;

static const size_t NH  = (size_t)NPX * CCH;
static const size_t NN  = (size_t)NPX * NPX;
static const size_t NQK = (size_t)NPX * 1024;
#define WS ((size_t)CCH * CCH)

// ---------------- static scratch ----------------
__device__ fp16  g_ht[(size_t)2 * NPX * CCH];    // GN output [B][N][C]
__device__ fp16  g_w[(size_t)4 * CCH * CCH];     // wq,wk,wv,wp fp16
__device__ fp16  g_wvT[(size_t)CCH * CCH];       // wv^T fp16
__device__ fp16  g_wpv[(size_t)CCH * CCH];       // Wpv = wp@wv fp16
__device__ float g_bpv[CCH];                     // wp@bv
__device__ float g_bqk[1024];                    // concat bq|bk
__device__ fp16  g_qk[(size_t)2 * NPX * 1024];   // [B][N][1024]: Q|K
__device__ fp16  g_wv16[(size_t)2 * CCH * NPX];  // WpV [B][C][N]
__device__ fp16  g_E[(size_t)2 * NPX * NPX];     // exp(scores) fp16
__device__ float g_part[(size_t)2 * NPX * 16];   // per-(row, nblock) partial sums

// ---------------- helpers ----------------
__device__ __forceinline__ uint32_t smem_u32(const void* p) {
    uint32_t a;
    asm("{ .reg .u64 t; cvta.to.shared.u64 t, %1; cvt.u32.u64 %0, t; }" : "=r"(a) : "l"(p));
    return a;
}
__device__ __forceinline__ uint32_t pack2(fp16 a, fp16 b) {
    __half2 t; t.x = a; t.y = b;
    return *reinterpret_cast<uint32_t*>(&t);
}
__device__ __forceinline__ void cp16(uint32_t s, const void* g) {
    asm volatile("cp.async.cg.shared.global [%0], [%1], 16;" :: "r"(s), "l"(g));
}
__device__ __forceinline__ void ldsm4(uint32_t* r, uint32_t addr) {
    asm volatile("ldmatrix.sync.aligned.m8n8.x4.shared.b16 {%0,%1,%2,%3}, [%4];"
        : "=r"(r[0]), "=r"(r[1]), "=r"(r[2]), "=r"(r[3]) : "r"(addr));
}
__device__ __forceinline__ void mma16816(float* d, const uint32_t* a, uint32_t b0, uint32_t b1) {
    asm volatile("mma.sync.aligned.m16n8k16.row.col.f32.f16.f16.f32 "
        "{%0,%1,%2,%3}, {%4,%5,%6,%7}, {%8,%9}, {%0,%1,%2,%3};"
        : "+f"(d[0]), "+f"(d[1]), "+f"(d[2]), "+f"(d[3])
        : "r"(a[0]), "r"(a[1]), "r"(a[2]), "r"(a[3]), "r"(b0), "r"(b1));
}

// ---------------- fused prep: GroupNorm FIRST, then wconv + wvT + bqk + bpv ----------------
// blocks [0,64):       GroupNorm (one per (b,g))   <- long blocks launch first
// blocks [64,4160):    elementwise fp16 convert of wq|wk|wv|wp
// blocks [4160,4416):  32x32 transpose tiles of wv (fp32 -> fp16 wvT)
// blocks [4416,4420):  bqk concat
// blocks [4420,4484):  bpv = wp@bv, warp per channel
__global__ void __launch_bounds__(256) prep_all(const float* __restrict__ wq,
                                                const float* __restrict__ wk,
                                                const float* __restrict__ wv,
                                                const float* __restrict__ wp,
                                                const float* __restrict__ bq,
                                                const float* __restrict__ bk,
                                                const float* __restrict__ bv,
                                                const float* __restrict__ x,
                                                const float* __restrict__ gamma,
                                                const float* __restrict__ beta) {
    int bid = blockIdx.x;
    int tid = threadIdx.x;
    if (bid < 64) {
        // ---- GroupNorm ----
        int b = bid >> 5;
        int g = bid & 31;
        const size_t base = ((size_t)b * CCH + (size_t)g * 16) * NPX;
        const float4* xp = (const float4*)(x + base);
        const int TOT4 = 16 * NPX / 4;

        float s = 0.f, ss = 0.f;
        for (int i = tid; i < TOT4; i += 256) {
            float4 v = xp[i];
            s  += v.x + v.y + v.z + v.w;
            ss += v.x * v.x + v.y * v.y + v.z * v.z + v.w * v.w;
        }
        __shared__ float rs[8], rss[8];
        #pragma unroll
        for (int o = 16; o > 0; o >>= 1) {
            s  += __shfl_xor_sync(0xffffffffu, s, o);
            ss += __shfl_xor_sync(0xffffffffu, ss, o);
        }
        if ((tid & 31) == 0) { rs[tid >> 5] = s; rss[tid >> 5] = ss; }
        __syncthreads();
        float S = 0.f, SS = 0.f;
        #pragma unroll
        for (int w = 0; w < 8; w++) { S += rs[w]; SS += rss[w]; }
        const float inv_cnt = 1.0f / (float)(16 * NPX);
        float mean = S * inv_cnt;
        float var  = SS * inv_cnt - mean * mean;
        float rstd = rsqrtf(var + 1e-6f);

        __shared__ float sga[16], sbe[16];
        if (tid < 16) {
            int c = g * 16 + tid;
            float ga = gamma[c] * rstd;
            sga[tid] = ga;
            sbe[tid] = beta[c] - mean * ga;
        }
        __shared__ float xs[16][256];
        __syncthreads();

        for (int p0 = 0; p0 < NPX; p0 += 256) {
            #pragma unroll
            for (int c = 0; c < 16; c++) xs[c][tid] = x[base + (size_t)c * NPX + p0 + tid];
            __syncthreads();
            uint32_t hw[8];
            #pragma unroll
            for (int c2 = 0; c2 < 8; c2++) {
                float v0 = xs[2 * c2][tid]     * sga[2 * c2]     + sbe[2 * c2];
                float v1 = xs[2 * c2 + 1][tid] * sga[2 * c2 + 1] + sbe[2 * c2 + 1];
                hw[c2] = pack2(__float2half(v0), __float2half(v1));
            }
            size_t o = ((size_t)b * NPX + p0 + tid) * CCH + g * 16;
            ((uint4*)(g_ht + o))[0] = make_uint4(hw[0], hw[1], hw[2], hw[3]);
            ((uint4*)(g_ht + o))[1] = make_uint4(hw[4], hw[5], hw[6], hw[7]);
            __syncthreads();
        }
        return;
    }
    if (bid < 4160) {
        size_t i = (size_t)(bid - 64) * 256 + tid;
        size_t which = i / WS, r = i - which * WS;
        const float* w = (which == 0) ? wq : (which == 1) ? wk : (which == 2) ? wv : wp;
        g_w[i] = __float2half(w[r]);
        return;
    }
    if (bid < 4416) {
        int t = bid - 4160;
        int bx = (t & 15) * 32, by = (t >> 4) * 32;
        int tx = tid & 31, ty = tid >> 5;    // 32 x 8
        __shared__ fp16 sm[32][33];
        #pragma unroll
        for (int r = 0; r < 32; r += 8)
            sm[ty + r][tx] = __float2half(wv[(size_t)(by + ty + r) * CCH + bx + tx]);
        __syncthreads();
        #pragma unroll
        for (int r = 0; r < 32; r += 8)
            g_wvT[(size_t)(bx + ty + r) * CCH + by + tx] = sm[tx][ty + r];
        return;
    }
    if (bid < 4420) {
        int i = (bid - 4416) * 256 + tid;
        g_bqk[i] = (i < 512) ? bq[i] : bk[i - 512];
        return;
    }
    {
        int wid = tid >> 5, lane = tid & 31;
        int c = (bid - 4420) * 8 + wid;
        const float* row = wp + (size_t)c * CCH;
        float s = 0.f;
        #pragma unroll
        for (int j = 0; j < 16; j++) s += row[lane + j * 32] * bv[lane + j * 32];
        #pragma unroll
        for (int o = 16; o > 0; o >>= 1) s += __shfl_xor_sync(0xffffffffu, s, o);
        if (lane == 0) g_bpv[c] = s;
    }
}

// ---------------- small GEMM: Wpv = wp @ wv  (512x512x512), CTA 64x64, grid 64 ----------------
#define SROWB 144
#define SSTG_A (64 * SROWB)
#define SSTG   (2 * SSTG_A)
__global__ void __launch_bounds__(256) wpv_gemm(const fp16* __restrict__ A,   // wp [512,512]
                                                const fp16* __restrict__ B,   // wvT [512,512]
                                                fp16* __restrict__ D) {
    extern __shared__ char smemraw[];
    int tid = threadIdx.x, wid = tid >> 5, lane = tid & 31;
    int m0 = (blockIdx.x >> 3) * 64, n0 = (blockIdx.x & 7) * 64;
    uint32_t base = smem_u32(smemraw);
    int wm = wid & 1, wn = wid >> 1;   // 2 x 4 warps; warp tile 32(m) x 16(n)

    float acc[2][2][4];
    #pragma unroll
    for (int a = 0; a < 2; a++)
        #pragma unroll
        for (int b = 0; b < 2; b++)
            #pragma unroll
            for (int c = 0; c < 4; c++) acc[a][b][c] = 0.f;

    auto load_chunk = [&](int i) {
        int st = i % 3;
        size_t kb = (size_t)i * 64;
        uint32_t sa = base + st * SSTG;
        uint32_t sb = sa + SSTG_A;
        #pragma unroll
        for (int r = 0; r < 2; r++) {
            int u = tid + r * 256;       // 0..511
            int row = u >> 3, cs = u & 7;
            cp16(sa + (uint32_t)(row * SROWB + cs * 16),
                 A + (size_t)(m0 + row) * CCH + kb + cs * 8);
            cp16(sb + (uint32_t)(row * SROWB + cs * 16),
                 B + (size_t)(n0 + row) * CCH + kb + cs * 8);
        }
    };

    load_chunk(0);
    asm volatile("cp.async.commit_group;" ::: "memory");
    load_chunk(1);
    asm volatile("cp.async.commit_group;" ::: "memory");

    uint32_t a_off[2], b_off;
    #pragma unroll
    for (int mi = 0; mi < 2; mi++) {
        int row = wm * 32 + mi * 16 + (lane & 15);
        a_off[mi] = (uint32_t)(row * SROWB + ((lane >> 4) * 8) * 2);
    }
    {
        int row = wn * 16 + ((lane >> 4) << 3) + (lane & 7);
        b_off = (uint32_t)(row * SROWB + ((((lane >> 3) & 1) << 3)) * 2);
    }

    const int nch = 8;
    for (int i = 0; i < nch; i++) {
        if (i < nch - 1) asm volatile("cp.async.wait_group 1;" ::: "memory");
        else             asm volatile("cp.async.wait_group 0;" ::: "memory");
        __syncthreads();
        if (i + 2 < nch) {
            load_chunk(i + 2);
            asm volatile("cp.async.commit_group;" ::: "memory");
        }
        uint32_t sa = base + (i % 3) * SSTG;
        uint32_t sb = sa + SSTG_A;

        #pragma unroll
        for (int kk = 0; kk < 4; kk++) {
            uint32_t ko = (uint32_t)(kk * 32);
            uint32_t afr[2][4], bfr[4];
            #pragma unroll
            for (int mi = 0; mi < 2; mi++) ldsm4(afr[mi], sa + a_off[mi] + ko);
            ldsm4(bfr, sb + b_off + ko);
            #pragma unroll
            for (int mi = 0; mi < 2; mi++)
                #pragma unroll
                for (int ni = 0; ni < 2; ni++)
                    mma16816(acc[mi][ni], afr[mi], bfr[ni * 2], bfr[ni * 2 + 1]);
        }
        __syncthreads();
    }

    int r4 = lane >> 2;
    int c2 = lane & 3;
    #pragma unroll
    for (int mi = 0; mi < 2; mi++)
        #pragma unroll
        for (int half = 0; half < 2; half++) {
            int m = m0 + wm * 32 + mi * 16 + half * 8 + r4;
            #pragma unroll
            for (int ni = 0; ni < 2; ni++) {
                int n = n0 + wn * 16 + ni * 8 + c2 * 2;
                *(uint32_t*)(D + (size_t)m * CCH + n) =
                    pack2(__float2half(acc[mi][ni][half * 2 + 0]),
                          __float2half(acc[mi][ni][half * 2 + 1]));
            }
        }
}

// ================= f32-acc GEMM: CTA 128x256, warp 64x64, BK=64, 3-stage =================
#define ROWB  144
#define STG_A (128 * ROWB)
#define STG_B (256 * ROWB)
#define STG   (STG_A + STG_B)

#define GEMM_MAINLOOP() \
    uint32_t base = smem_u32(smemraw); \
    int wm = wid & 1, wn = wid >> 1; \
    const int nch = K >> 6; \
    float acc[4][8][4]; \
    _Pragma("unroll") \
    for (int a_ = 0; a_ < 4; a_++) \
        _Pragma("unroll") \
        for (int b_ = 0; b_ < 8; b_++) \
            _Pragma("unroll") \
            for (int c_ = 0; c_ < 4; c_++) acc[a_][b_][c_] = 0.f; \
    auto load_chunk = [&](int i) { \
        int st = i % 3; \
        size_t kb = (size_t)i * 64; \
        uint32_t sa = base + st * STG; \
        uint32_t sb = sa + STG_A; \
        _Pragma("unroll") \
        for (int r = 0; r < 4; r++) { \
            int u = tid + r * 256; \
            int row = u >> 3, cs = u & 7; \
            cp16(sa + (uint32_t)(row * ROWB + cs * 16), \
                 A + (size_t)(m0 + row) * ldA + kb + cs * 8); \
        } \
        _Pragma("unroll") \
        for (int r = 0; r < 8; r++) { \
            int u = tid + r * 256; \
            int row = u >> 3, cs = u & 7; \
            cp16(sb + (uint32_t)(row * ROWB + cs * 16), \
                 B + (size_t)(n0 + row) * ldB + kb + cs * 8); \
        } \
    }; \
    load_chunk(0); \
    asm volatile("cp.async.commit_group;" ::: "memory"); \
    if (nch > 1) load_chunk(1); \
    asm volatile("cp.async.commit_group;" ::: "memory"); \
    uint32_t a_off[4], b_off[4]; \
    _Pragma("unroll") \
    for (int mi = 0; mi < 4; mi++) { \
        int row = wm * 64 + mi * 16 + (lane & 15); \
        a_off[mi] = (uint32_t)(row * ROWB + ((lane >> 4) * 8) * 2); \
    } \
    _Pragma("unroll") \
    for (int nb = 0; nb < 4; nb++) { \
        int row = wn * 64 + nb * 16 + ((lane >> 4) << 3) + (lane & 7); \
        b_off[nb] = (uint32_t)(row * ROWB + ((((lane >> 3) & 1) << 3)) * 2); \
    } \
    for (int i = 0; i < nch; i++) { \
        if (i < nch - 1) asm volatile("cp.async.wait_group 1;" ::: "memory"); \
        else             asm volatile("cp.async.wait_group 0;" ::: "memory"); \
        __syncthreads(); \
        if (i + 2 < nch) { \
            load_chunk(i + 2); \
            asm volatile("cp.async.commit_group;" ::: "memory"); \
        } \
        uint32_t sa = base + (i % 3) * STG; \
        uint32_t sb = sa + STG_A; \
        uint32_t afr[2][4][4], bfr[2][4][4]; \
        _Pragma("unroll") \
        for (int mi = 0; mi < 4; mi++) ldsm4(afr[0][mi], sa + a_off[mi]); \
        _Pragma("unroll") \
        for (int nb = 0; nb < 4; nb++) ldsm4(bfr[0][nb], sb + b_off[nb]); \
        _Pragma("unroll") \
        for (int kk = 0; kk < 4; kk++) { \
            int cur = kk & 1, nxt = cur ^ 1; \
            if (kk < 3) { \
                uint32_t ko = (uint32_t)((kk + 1) * 32); \
                _Pragma("unroll") \
                for (int mi = 0; mi < 4; mi++) ldsm4(afr[nxt][mi], sa + a_off[mi] + ko); \
                _Pragma("unroll") \
                for (int nb = 0; nb < 4; nb++) ldsm4(bfr[nxt][nb], sb + b_off[nb] + ko); \
            } \
            _Pragma("unroll") \
            for (int mi = 0; mi < 4; mi++) \
                _Pragma("unroll") \
                for (int ni = 0; ni < 8; ni++) \
                    mma16816(acc[mi][ni], afr[cur][mi], \
                             bfr[cur][ni >> 1][(ni & 1) * 2], bfr[cur][ni >> 1][(ni & 1) * 2 + 1]); \
        } \
    }

// ---- merged QK + WpV GEMM (both K=512, fp16 out). 1-D grid of 384 blocks:
// blocks [0,256):  QK  tile: b=idx/128, m0=((idx%128)/4)*128, n0=(idx%4)*256
//                  D[b][m][n] = sum_k ht[b][m][k]*w[n][k] + bqk[n]
// blocks [256,384): WpV tile: idx2=idx-256, b=idx2/64, m0=((idx2%64)/16)*128, n0=(idx2%16)*256
//                  D[b][m][n] = sum_k wpv[m][k]*ht[b][n][k] + bpv[m]
__global__ void gemm_qkwpv(const fp16* __restrict__ ht,
                           const fp16* __restrict__ w,
                           const fp16* __restrict__ wpv,
                           fp16* __restrict__ qk,
                           fp16* __restrict__ wv16,
                           const float* __restrict__ bqk,
                           const float* __restrict__ bpv)
{
    extern __shared__ char smemraw[];
    int tid = threadIdx.x, wid = tid >> 5, lane = tid & 31;
    const int K = 512;

    const fp16 *A, *B;
    int ldA, ldB, m0, n0;
    bool isQK = (blockIdx.x < 256);
    int bz;
    fp16* outp;
    int ldD;
    if (isQK) {
        int idx = blockIdx.x;
        bz = idx >> 7;
        int rem = idx & 127;
        m0 = (rem >> 2) * 128;
        n0 = (rem & 3) * 256;
        A = ht + (size_t)bz * NH; ldA = CCH;
        B = w;                    ldB = CCH;
        outp = qk + (size_t)bz * NQK; ldD = 1024;
    } else {
        int idx = blockIdx.x - 256;
        bz = idx >> 6;
        int rem = idx & 63;
        m0 = (rem >> 4) * 128;
        n0 = (rem & 15) * 256;
        A = wpv;                  ldA = CCH;
        B = ht + (size_t)bz * NH; ldB = CCH;
        outp = wv16 + (size_t)bz * NH; ldD = NPX;
    }

    GEMM_MAINLOOP()

    int r4 = lane >> 2;
    int c2 = lane & 3;

    #pragma unroll
    for (int mi = 0; mi < 4; mi++) {
        #pragma unroll
        for (int half = 0; half < 2; half++) {
            int m = m0 + wm * 64 + mi * 16 + half * 8 + r4;
            float brow = isQK ? 0.f : bpv[m];
            #pragma unroll
            for (int ni = 0; ni < 8; ni++) {
                int n = n0 + wn * 64 + ni * 8 + c2 * 2;
                float v0 = acc[mi][ni][half * 2 + 0] + brow;
                float v1 = acc[mi][ni][half * 2 + 1] + brow;
                if (isQK) { v0 += bqk[n]; v1 += bqk[n + 1]; }
                *(uint32_t*)(outp + (size_t)m * ldD + n) = pack2(__float2half(v0), __float2half(v1));
            }
        }
    }
}

// ---- scores GEMM: E=exp(scale*s) fp16 + per-row partial sums ----
__global__ void gemm_scores(
    const fp16* __restrict__ A, int ldA, size_t strideA,
    const fp16* __restrict__ B, int ldB, size_t strideB,
    int K,
    fp16* __restrict__ outE, int ldD, size_t strideD,
    float scale)
{
    extern __shared__ char smemraw[];
    int tid = threadIdx.x, wid = tid >> 5, lane = tid & 31;
    int m0 = blockIdx.y * 128, n0 = blockIdx.x * 256, bz = blockIdx.z;
    A += (size_t)bz * strideA;
    B += (size_t)bz * strideB;

    GEMM_MAINLOOP()

    int r4 = lane >> 2;
    int c2 = lane & 3;
    fp16* oh = outE + (size_t)bz * strideD;
    float rsum[8];
    #pragma unroll
    for (int r = 0; r < 8; r++) rsum[r] = 0.f;

    #pragma unroll
    for (int mi = 0; mi < 4; mi++) {
        #pragma unroll
        for (int half = 0; half < 2; half++) {
            int m = m0 + wm * 64 + mi * 16 + half * 8 + r4;
            float rs = 0.f;
            #pragma unroll
            for (int ni = 0; ni < 8; ni++) {
                int n = n0 + wn * 64 + ni * 8 + c2 * 2;
                float e0 = __expf(acc[mi][ni][half * 2 + 0] * scale);
                float e1 = __expf(acc[mi][ni][half * 2 + 1] * scale);
                *(uint32_t*)(oh + (size_t)m * ldD + n) = pack2(__float2half(e0), __float2half(e1));
                rs += e0 + e1;
            }
            rsum[mi * 2 + half] = rs;
        }
    }
    #pragma unroll
    for (int r = 0; r < 8; r++) {
        rsum[r] += __shfl_xor_sync(0xffffffffu, rsum[r], 1);
        rsum[r] += __shfl_xor_sync(0xffffffffu, rsum[r], 2);
    }
    __syncthreads();
    float* sp = (float*)smemraw;
    if (c2 == 0) {
        #pragma unroll
        for (int mi = 0; mi < 4; mi++)
            #pragma unroll
            for (int half = 0; half < 2; half++) {
                int rl = wm * 64 + mi * 16 + half * 8 + r4;
                sp[rl * 4 + wn] = rsum[mi * 2 + half];
            }
    }
    __syncthreads();
    if (tid < 128) {
        float s = sp[tid * 4] + sp[tid * 4 + 1] + sp[tid * 4 + 2] + sp[tid * 4 + 3];
        g_part[((size_t)bz * NPX + m0 + tid) * 16 + blockIdx.x] = s;
    }
}

// ---- final GEMM: out = (WpV @ E^T) * inv_rowsum + biasRow + resid ----
__global__ void gemm_final(
    const fp16* __restrict__ A, int ldA, size_t strideA,
    const fp16* __restrict__ B, int ldB, size_t strideB,
    int K,
    float* __restrict__ outF32, int ldD, size_t strideD,
    const float* __restrict__ biasRow,
    const float* __restrict__ resid)
{
    extern __shared__ char smemraw[];
    int tid = threadIdx.x, wid = tid >> 5, lane = tid & 31;
    int m0 = blockIdx.y * 128, n0 = blockIdx.x * 256, bz = blockIdx.z;
    A += (size_t)bz * strideA;
    B += (size_t)bz * strideB;

    GEMM_MAINLOOP()

    // inverse row sums for this CTA's 256 columns
    float* sp = (float*)smemraw;
    {
        const float* p = g_part + ((size_t)bz * NPX + n0 + tid) * 16;
        float s = 0.f;
        #pragma unroll
        for (int k = 0; k < 16; k++) s += p[k];
        sp[tid] = 1.0f / s;
    }
    __syncthreads();

    int r4 = lane >> 2;
    int c2 = lane & 3;
    float* of = outF32 + (size_t)bz * strideD;
    const float* rp = resid + (size_t)bz * strideD;

    #pragma unroll
    for (int mi = 0; mi < 4; mi++) {
        #pragma unroll
        for (int half = 0; half < 2; half++) {
            int m = m0 + wm * 64 + mi * 16 + half * 8 + r4;
            float brow = biasRow[m];
            #pragma unroll
            for (int ni = 0; ni < 8; ni++) {
                int n = n0 + wn * 64 + ni * 8 + c2 * 2;
                float v0 = acc[mi][ni][half * 2 + 0] * sp[n - n0]     + brow;
                float v1 = acc[mi][ni][half * 2 + 1] * sp[n + 1 - n0] + brow;
                size_t off = (size_t)m * ldD + n;
                float2 q = *(const float2*)(rp + off);
                v0 += q.x; v1 += q.y;
                *(float2*)(of + off) = make_float2(v0, v1);
            }
        }
    }
}

// ---------------- launch ----------------
extern "C" void kernel_launch(void* const* d_in, const int* in_sizes, int n_in,
                              void* d_out, int out_size) {
    const float* x     = (const float*)d_in[0];
    const float* gamma = (const float*)d_in[1];
    const float* beta  = (const float*)d_in[2];
    const float* wq    = (const float*)d_in[3];
    const float* bq    = (const float*)d_in[4];
    const float* wk    = (const float*)d_in[5];
    const float* bk    = (const float*)d_in[6];
    const float* wv    = (const float*)d_in[7];
    const float* bv    = (const float*)d_in[8];
    const float* wp    = (const float*)d_in[9];
    const float* bp    = (const float*)d_in[10];
    float* out = (float*)d_out;

    fp16 *ht, *w, *wvT, *wpv, *qk, *wv16, *E;
    float *bqk, *bpv;
    cudaGetSymbolAddress((void**)&ht, g_ht);
    cudaGetSymbolAddress((void**)&w, g_w);
    cudaGetSymbolAddress((void**)&wvT, g_wvT);
    cudaGetSymbolAddress((void**)&wpv, g_wpv);
    cudaGetSymbolAddress((void**)&qk, g_qk);
    cudaGetSymbolAddress((void**)&wv16, g_wv16);
    cudaGetSymbolAddress((void**)&E, g_E);
    cudaGetSymbolAddress((void**)&bqk, g_bqk);
    cudaGetSymbolAddress((void**)&bpv, g_bpv);

    const int SMEM_DYN = 3 * STG;      // 162 KB
    const int SMEM_WPV = 3 * SSTG;     // 55 KB
    cudaFuncSetAttribute(gemm_qkwpv, cudaFuncAttributeMaxDynamicSharedMemorySize, SMEM_DYN);
    cudaFuncSetAttribute(gemm_scores, cudaFuncAttributeMaxDynamicSharedMemorySize, SMEM_DYN);
    cudaFuncSetAttribute(gemm_final, cudaFuncAttributeMaxDynamicSharedMemorySize, SMEM_DYN);
    cudaFuncSetAttribute(wpv_gemm, cudaFuncAttributeMaxDynamicSharedMemorySize, SMEM_WPV);

    // fused prep (gn first) 
    prep_all<<<4484, 256>>>(wq, wk, wv, wp, bq, bk, bv, x, gamma, beta);

    // Wpv = wp @ wv : [512,512] fp16, 64 CTAs
    wpv_gemm<<<64, 256, SMEM_WPV>>>(w + 3 * WS, wvT, wpv);

    // merged QK + WpV : 384 CTAs
    gemm_qkwpv<<<384, 256, SMEM_DYN>>>(ht, w, wpv, qk, wv16, bqk, bpv);

    // scores -> E = exp(scale * Q@K^T) fp16 + partial sums
    const float scale = 1.0f / sqrtf((float)CCH);
    gemm_scores<<<dim3(NPX / 256, NPX / 128, 2), 256, SMEM_DYN>>>(
        qk, 1024, NQK, qk + 512, 1024, NQK, CCH,
        E, NPX, NN, scale);

    // final: out[c,i] = (sum_j WpV[c,j]*E[i,j]) * invs[i] + bp[c] + x[c,i]
    gemm_final<<<dim3(NPX / 256, CCH / 128, 2), 256, SMEM_DYN>>>(
        wv16, NPX, NH, E, NPX, NN, NPX,
        out, NPX, (size_t)CCH * NPX, bp, x);
}

// round 14
// speedup vs baseline: 1.0828x; 1.0128x over previous
#include <cuda_runtime.h>
#include <cuda_fp16.h>
#include <math.h>
#include <stdint.h>

#define CCH 512
#define NPX 4096
typedef __half fp16;

static const size_t NH  = (size_t)NPX * CCH;
static const size_t NN  = (size_t)NPX * NPX;
static const size_t NQK = (size_t)NPX * 1024;
#define WS ((size_t)CCH * CCH)

// ---------------- static scratch ----------------
__device__ fp16  g_ht[(size_t)2 * NPX * CCH];    // GN output [B][N][C]
__device__ fp16  g_w[(size_t)4 * CCH * CCH];     // wq,wk,wv,wp fp16
__device__ fp16  g_wvT[(size_t)CCH * CCH];       // wv^T fp16
__device__ fp16  g_wpv[(size_t)CCH * CCH];       // Wpv = wp@wv fp16
__device__ float g_bpv[CCH];                     // wp@bv
__device__ float g_bqk[1024];                    // concat bq|bk
__device__ fp16  g_qk[(size_t)2 * NPX * 1024];   // [B][N][1024]: Q|K
__device__ fp16  g_wv16[(size_t)2 * CCH * NPX];  // WpV [B][C][N]
__device__ fp16  g_E[(size_t)2 * NPX * NPX];     // exp(scores) fp16
__device__ float g_part[(size_t)2 * NPX * 16];   // per-(row, nblock) partial sums

// ---------------- helpers ----------------
__device__ __forceinline__ uint32_t smem_u32(const void* p) {
    uint32_t a;
    asm("{ .reg .u64 t; cvta.to.shared.u64 t, %1; cvt.u32.u64 %0, t; }" : "=r"(a) : "l"(p));
    return a;
}
__device__ __forceinline__ uint32_t pack2(fp16 a, fp16 b) {
    __half2 t; t.x = a; t.y = b;
    return *reinterpret_cast<uint32_t*>(&t);
}
__device__ __forceinline__ void cp16(uint32_t s, const void* g) {
    asm volatile("cp.async.cg.shared.global [%0], [%1], 16;" :: "r"(s), "l"(g));
}
__device__ __forceinline__ void ldsm4(uint32_t* r, uint32_t addr) {
    asm volatile("ldmatrix.sync.aligned.m8n8.x4.shared.b16 {%0,%1,%2,%3}, [%4];"
        : "=r"(r[0]), "=r"(r[1]), "=r"(r[2]), "=r"(r[3]) : "r"(addr));
}
__device__ __forceinline__ void mma16816(float* d, const uint32_t* a, uint32_t b0, uint32_t b1) {
    asm volatile("mma.sync.aligned.m16n8k16.row.col.f32.f16.f16.f32 "
        "{%0,%1,%2,%3}, {%4,%5,%6,%7}, {%8,%9}, {%0,%1,%2,%3};"
        : "+f"(d[0]), "+f"(d[1]), "+f"(d[2]), "+f"(d[3])
        : "r"(a[0]), "r"(a[1]), "r"(a[2]), "r"(a[3]), "r"(b0), "r"(b1));
}

// ---------------- fused prep: GroupNorm FIRST, then wconv + wvT + bqk + bpv ----------------
__global__ void __launch_bounds__(256) prep_all(const float* __restrict__ wq,
                                                const float* __restrict__ wk,
                                                const float* __restrict__ wv,
                                                const float* __restrict__ wp,
                                                const float* __restrict__ bq,
                                                const float* __restrict__ bk,
                                                const float* __restrict__ bv,
                                                const float* __restrict__ x,
                                                const float* __restrict__ gamma,
                                                const float* __restrict__ beta) {
    int bid = blockIdx.x;
    int tid = threadIdx.x;
    if (bid < 64) {
        // ---- GroupNorm ----
        int b = bid >> 5;
        int g = bid & 31;
        const size_t base = ((size_t)b * CCH + (size_t)g * 16) * NPX;
        const float4* xp = (const float4*)(x + base);
        const int TOT4 = 16 * NPX / 4;

        float s = 0.f, ss = 0.f;
        for (int i = tid; i < TOT4; i += 256) {
            float4 v = xp[i];
            s  += v.x + v.y + v.z + v.w;
            ss += v.x * v.x + v.y * v.y + v.z * v.z + v.w * v.w;
        }
        __shared__ float rs[8], rss[8];
        #pragma unroll
        for (int o = 16; o > 0; o >>= 1) {
            s  += __shfl_xor_sync(0xffffffffu, s, o);
            ss += __shfl_xor_sync(0xffffffffu, ss, o);
        }
        if ((tid & 31) == 0) { rs[tid >> 5] = s; rss[tid >> 5] = ss; }
        __syncthreads();
        float S = 0.f, SS = 0.f;
        #pragma unroll
        for (int w = 0; w < 8; w++) { S += rs[w]; SS += rss[w]; }
        const float inv_cnt = 1.0f / (float)(16 * NPX);
        float mean = S * inv_cnt;
        float var  = SS * inv_cnt - mean * mean;
        float rstd = rsqrtf(var + 1e-6f);

        __shared__ float sga[16], sbe[16];
        if (tid < 16) {
            int c = g * 16 + tid;
            float ga = gamma[c] * rstd;
            sga[tid] = ga;
            sbe[tid] = beta[c] - mean * ga;
        }
        __shared__ float xs[16][256];
        __syncthreads();

        for (int p0 = 0; p0 < NPX; p0 += 256) {
            #pragma unroll
            for (int c = 0; c < 16; c++) xs[c][tid] = x[base + (size_t)c * NPX + p0 + tid];
            __syncthreads();
            uint32_t hw[8];
            #pragma unroll
            for (int c2 = 0; c2 < 8; c2++) {
                float v0 = xs[2 * c2][tid]     * sga[2 * c2]     + sbe[2 * c2];
                float v1 = xs[2 * c2 + 1][tid] * sga[2 * c2 + 1] + sbe[2 * c2 + 1];
                hw[c2] = pack2(__float2half(v0), __float2half(v1));
            }
            size_t o = ((size_t)b * NPX + p0 + tid) * CCH + g * 16;
            ((uint4*)(g_ht + o))[0] = make_uint4(hw[0], hw[1], hw[2], hw[3]);
            ((uint4*)(g_ht + o))[1] = make_uint4(hw[4], hw[5], hw[6], hw[7]);
            __syncthreads();
        }
        return;
    }
    if (bid < 4160) {
        size_t i = (size_t)(bid - 64) * 256 + tid;
        size_t which = i / WS, r = i - which * WS;
        const float* w = (which == 0) ? wq : (which == 1) ? wk : (which == 2) ? wv : wp;
        g_w[i] = __float2half(w[r]);
        return;
    }
    if (bid < 4416) {
        int t = bid - 4160;
        int bx = (t & 15) * 32, by = (t >> 4) * 32;
        int tx = tid & 31, ty = tid >> 5;    // 32 x 8
        __shared__ fp16 sm[32][33];
        #pragma unroll
        for (int r = 0; r < 32; r += 8)
            sm[ty + r][tx] = __float2half(wv[(size_t)(by + ty + r) * CCH + bx + tx]);
        __syncthreads();
        #pragma unroll
        for (int r = 0; r < 32; r += 8)
            g_wvT[(size_t)(bx + ty + r) * CCH + by + tx] = sm[tx][ty + r];
        return;
    }
    if (bid < 4420) {
        int i = (bid - 4416) * 256 + tid;
        g_bqk[i] = (i < 512) ? bq[i] : bk[i - 512];
        return;
    }
    {
        int wid = tid >> 5, lane = tid & 31;
        int c = (bid - 4420) * 8 + wid;
        const float* row = wp + (size_t)c * CCH;
        float s = 0.f;
        #pragma unroll
        for (int j = 0; j < 16; j++) s += row[lane + j * 32] * bv[lane + j * 32];
        #pragma unroll
        for (int o = 16; o > 0; o >>= 1) s += __shfl_xor_sync(0xffffffffu, s, o);
        if (lane == 0) g_bpv[c] = s;
    }
}

// ---------------- small GEMM: Wpv = wp @ wv  (512x512x512), CTA 64x64, grid 64 ----------------
#define SROWB 144
#define SSTG_A (64 * SROWB)
#define SSTG   (2 * SSTG_A)
__global__ void __launch_bounds__(256) wpv_gemm(const fp16* __restrict__ A,
                                                const fp16* __restrict__ B,
                                                fp16* __restrict__ D) {
    extern __shared__ char smemraw[];
    int tid = threadIdx.x, wid = tid >> 5, lane = tid & 31;
    int m0 = (blockIdx.x >> 3) * 64, n0 = (blockIdx.x & 7) * 64;
    uint32_t base = smem_u32(smemraw);
    int wm = wid & 1, wn = wid >> 1;

    float acc[2][2][4];
    #pragma unroll
    for (int a = 0; a < 2; a++)
        #pragma unroll
        for (int b = 0; b < 2; b++)
            #pragma unroll
            for (int c = 0; c < 4; c++) acc[a][b][c] = 0.f;

    auto load_chunk = [&](int i) {
        int st = i % 3;
        size_t kb = (size_t)i * 64;
        uint32_t sa = base + st * SSTG;
        uint32_t sb = sa + SSTG_A;
        #pragma unroll
        for (int r = 0; r < 2; r++) {
            int u = tid + r * 256;
            int row = u >> 3, cs = u & 7;
            cp16(sa + (uint32_t)(row * SROWB + cs * 16),
                 A + (size_t)(m0 + row) * CCH + kb + cs * 8);
            cp16(sb + (uint32_t)(row * SROWB + cs * 16),
                 B + (size_t)(n0 + row) * CCH + kb + cs * 8);
        }
    };

    load_chunk(0);
    asm volatile("cp.async.commit_group;" ::: "memory");
    load_chunk(1);
    asm volatile("cp.async.commit_group;" ::: "memory");

    uint32_t a_off[2], b_off;
    #pragma unroll
    for (int mi = 0; mi < 2; mi++) {
        int row = wm * 32 + mi * 16 + (lane & 15);
        a_off[mi] = (uint32_t)(row * SROWB + ((lane >> 4) * 8) * 2);
    }
    {
        int row = wn * 16 + ((lane >> 4) << 3) + (lane & 7);
        b_off = (uint32_t)(row * SROWB + ((((lane >> 3) & 1) << 3)) * 2);
    }

    const int nch = 8;
    for (int i = 0; i < nch; i++) {
        if (i < nch - 1) asm volatile("cp.async.wait_group 1;" ::: "memory");
        else             asm volatile("cp.async.wait_group 0;" ::: "memory");
        __syncthreads();
        if (i + 2 < nch) {
            load_chunk(i + 2);
            asm volatile("cp.async.commit_group;" ::: "memory");
        }
        uint32_t sa = base + (i % 3) * SSTG;
        uint32_t sb = sa + SSTG_A;

        #pragma unroll
        for (int kk = 0; kk < 4; kk++) {
            uint32_t ko = (uint32_t)(kk * 32);
            uint32_t afr[2][4], bfr[4];
            #pragma unroll
            for (int mi = 0; mi < 2; mi++) ldsm4(afr[mi], sa + a_off[mi] + ko);
            ldsm4(bfr, sb + b_off + ko);
            #pragma unroll
            for (int mi = 0; mi < 2; mi++)
                #pragma unroll
                for (int ni = 0; ni < 2; ni++)
                    mma16816(acc[mi][ni], afr[mi], bfr[ni * 2], bfr[ni * 2 + 1]);
        }
        __syncthreads();
    }

    int r4 = lane >> 2;
    int c2 = lane & 3;
    #pragma unroll
    for (int mi = 0; mi < 2; mi++)
        #pragma unroll
        for (int half = 0; half < 2; half++) {
            int m = m0 + wm * 32 + mi * 16 + half * 8 + r4;
            #pragma unroll
            for (int ni = 0; ni < 2; ni++) {
                int n = n0 + wn * 16 + ni * 8 + c2 * 2;
                *(uint32_t*)(D + (size_t)m * CCH + n) =
                    pack2(__float2half(acc[mi][ni][half * 2 + 0]),
                          __float2half(acc[mi][ni][half * 2 + 1]));
            }
        }
}

// ================= big-tile GEMM (scores only): CTA 128x256, 3-stage =================
#define ROWB  144
#define STG_A (128 * ROWB)
#define STG_B (256 * ROWB)
#define STG   (STG_A + STG_B)

#define GEMM_MAINLOOP() \
    uint32_t base = smem_u32(smemraw); \
    int wm = wid & 1, wn = wid >> 1; \
    const int nch = K >> 6; \
    float acc[4][8][4]; \
    _Pragma("unroll") \
    for (int a_ = 0; a_ < 4; a_++) \
        _Pragma("unroll") \
        for (int b_ = 0; b_ < 8; b_++) \
            _Pragma("unroll") \
            for (int c_ = 0; c_ < 4; c_++) acc[a_][b_][c_] = 0.f; \
    auto load_chunk = [&](int i) { \
        int st = i % 3; \
        size_t kb = (size_t)i * 64; \
        uint32_t sa = base + st * STG; \
        uint32_t sb = sa + STG_A; \
        _Pragma("unroll") \
        for (int r = 0; r < 4; r++) { \
            int u = tid + r * 256; \
            int row = u >> 3, cs = u & 7; \
            cp16(sa + (uint32_t)(row * ROWB + cs * 16), \
                 A + (size_t)(m0 + row) * ldA + kb + cs * 8); \
        } \
        _Pragma("unroll") \
        for (int r = 0; r < 8; r++) { \
            int u = tid + r * 256; \
            int row = u >> 3, cs = u & 7; \
            cp16(sb + (uint32_t)(row * ROWB + cs * 16), \
                 B + (size_t)(n0 + row) * ldB + kb + cs * 8); \
        } \
    }; \
    load_chunk(0); \
    asm volatile("cp.async.commit_group;" ::: "memory"); \
    if (nch > 1) load_chunk(1); \
    asm volatile("cp.async.commit_group;" ::: "memory"); \
    uint32_t a_off[4], b_off[4]; \
    _Pragma("unroll") \
    for (int mi = 0; mi < 4; mi++) { \
        int row = wm * 64 + mi * 16 + (lane & 15); \
        a_off[mi] = (uint32_t)(row * ROWB + ((lane >> 4) * 8) * 2); \
    } \
    _Pragma("unroll") \
    for (int nb = 0; nb < 4; nb++) { \
        int row = wn * 64 + nb * 16 + ((lane >> 4) << 3) + (lane & 7); \
        b_off[nb] = (uint32_t)(row * ROWB + ((((lane >> 3) & 1) << 3)) * 2); \
    } \
    for (int i = 0; i < nch; i++) { \
        if (i < nch - 1) asm volatile("cp.async.wait_group 1;" ::: "memory"); \
        else             asm volatile("cp.async.wait_group 0;" ::: "memory"); \
        __syncthreads(); \
        if (i + 2 < nch) { \
            load_chunk(i + 2); \
            asm volatile("cp.async.commit_group;" ::: "memory"); \
        } \
        uint32_t sa = base + (i % 3) * STG; \
        uint32_t sb = sa + STG_A; \
        uint32_t afr[2][4][4], bfr[2][4][4]; \
        _Pragma("unroll") \
        for (int mi = 0; mi < 4; mi++) ldsm4(afr[0][mi], sa + a_off[mi]); \
        _Pragma("unroll") \
        for (int nb = 0; nb < 4; nb++) ldsm4(bfr[0][nb], sb + b_off[nb]); \
        _Pragma("unroll") \
        for (int kk = 0; kk < 4; kk++) { \
            int cur = kk & 1, nxt = cur ^ 1; \
            if (kk < 3) { \
                uint32_t ko = (uint32_t)((kk + 1) * 32); \
                _Pragma("unroll") \
                for (int mi = 0; mi < 4; mi++) ldsm4(afr[nxt][mi], sa + a_off[mi] + ko); \
                _Pragma("unroll") \
                for (int nb = 0; nb < 4; nb++) ldsm4(bfr[nxt][nb], sb + b_off[nb] + ko); \
            } \
            _Pragma("unroll") \
            for (int mi = 0; mi < 4; mi++) \
                _Pragma("unroll") \
                for (int ni = 0; ni < 8; ni++) \
                    mma16816(acc[mi][ni], afr[cur][mi], \
                             bfr[cur][ni >> 1][(ni & 1) * 2], bfr[cur][ni >> 1][(ni & 1) * 2 + 1]); \
        } \
    }

// ================= mid-tile GEMM: CTA 128x128, warp 64x32, 2-stage, 2 CTAs/SM =================
#define T2STG_A (128 * ROWB)        // 18432
#define T2STG   (2 * T2STG_A)       // 36864 per stage; x2 stages = 73728

#define GEMM2_MAINLOOP() \
    uint32_t base = smem_u32(smemraw); \
    int wm = wid & 1, wn = wid >> 1; \
    const int nch = K >> 6; \
    float acc[4][4][4]; \
    _Pragma("unroll") \
    for (int a_ = 0; a_ < 4; a_++) \
        _Pragma("unroll") \
        for (int b_ = 0; b_ < 4; b_++) \
            _Pragma("unroll") \
            for (int c_ = 0; c_ < 4; c_++) acc[a_][b_][c_] = 0.f; \
    auto load_chunk = [&](int i) { \
        int st = i & 1; \
        size_t kb = (size_t)i * 64; \
        uint32_t sa = base + st * T2STG; \
        uint32_t sb = sa + T2STG_A; \
        _Pragma("unroll") \
        for (int r = 0; r < 4; r++) { \
            int u = tid + r * 256; \
            int row = u >> 3, cs = u & 7; \
            cp16(sa + (uint32_t)(row * ROWB + cs * 16), \
                 A + (size_t)(m0 + row) * ldA + kb + cs * 8); \
            cp16(sb + (uint32_t)(row * ROWB + cs * 16), \
                 B + (size_t)(n0 + row) * ldB + kb + cs * 8); \
        } \
    }; \
    load_chunk(0); \
    asm volatile("cp.async.commit_group;" ::: "memory"); \
    uint32_t a_off[4], b_off[2]; \
    _Pragma("unroll") \
    for (int mi = 0; mi < 4; mi++) { \
        int row = wm * 64 + mi * 16 + (lane & 15); \
        a_off[mi] = (uint32_t)(row * ROWB + ((lane >> 4) * 8) * 2); \
    } \
    _Pragma("unroll") \
    for (int nb = 0; nb < 2; nb++) { \
        int row = wn * 32 + nb * 16 + ((lane >> 4) << 3) + (lane & 7); \
        b_off[nb] = (uint32_t)(row * ROWB + ((((lane >> 3) & 1) << 3)) * 2); \
    } \
    for (int i = 0; i < nch; i++) { \
        if (i + 1 < nch) { \
            load_chunk(i + 1); \
            asm volatile("cp.async.commit_group;" ::: "memory"); \
            asm volatile("cp.async.wait_group 1;" ::: "memory"); \
        } else { \
            asm volatile("cp.async.wait_group 0;" ::: "memory"); \
        } \
        __syncthreads(); \
        uint32_t sa = base + (i & 1) * T2STG; \
        uint32_t sb = sa + T2STG_A; \
        uint32_t afr[2][4][4], bfr[2][2][4]; \
        _Pragma("unroll") \
        for (int mi = 0; mi < 4; mi++) ldsm4(afr[0][mi], sa + a_off[mi]); \
        _Pragma("unroll") \
        for (int nb = 0; nb < 2; nb++) ldsm4(bfr[0][nb], sb + b_off[nb]); \
        _Pragma("unroll") \
        for (int kk = 0; kk < 4; kk++) { \
            int cur = kk & 1, nxt = cur ^ 1; \
            if (kk < 3) { \
                uint32_t ko = (uint32_t)((kk + 1) * 32); \
                _Pragma("unroll") \
                for (int mi = 0; mi < 4; mi++) ldsm4(afr[nxt][mi], sa + a_off[mi] + ko); \
                _Pragma("unroll") \
                for (int nb = 0; nb < 2; nb++) ldsm4(bfr[nxt][nb], sb + b_off[nb] + ko); \
            } \
            _Pragma("unroll") \
            for (int mi = 0; mi < 4; mi++) \
                _Pragma("unroll") \
                for (int ni = 0; ni < 4; ni++) \
                    mma16816(acc[mi][ni], afr[cur][mi], \
                             bfr[cur][ni >> 1][(ni & 1) * 2], bfr[cur][ni >> 1][(ni & 1) * 2 + 1]); \
        } \
        __syncthreads(); \
    }

// ---- merged QK + WpV GEMM (mid tiles, 768 blocks) ----
// blocks [0,512):  QK: bz=idx>>8; rem=idx&255; m0=(rem>>3)*128; n0=(rem&7)*128
// blocks [512,768): WpV: idx2=idx-512; bz=idx2>>7; rem=idx2&127; m0=(rem>>5)*128; n0=(rem&31)*128
__global__ void __launch_bounds__(256, 2) gemm_qkwpv(const fp16* __restrict__ ht,
                                                     const fp16* __restrict__ w,
                                                     const fp16* __restrict__ wpv,
                                                     fp16* __restrict__ qk,
                                                     fp16* __restrict__ wv16,
                                                     const float* __restrict__ bqk,
                                                     const float* __restrict__ bpv)
{
    extern __shared__ char smemraw[];
    int tid = threadIdx.x, wid = tid >> 5, lane = tid & 31;
    const int K = 512;

    const fp16 *A, *B;
    int ldA, ldB, m0, n0;
    bool isQK = (blockIdx.x < 512);
    int bz;
    fp16* outp;
    int ldD;
    if (isQK) {
        int idx = blockIdx.x;
        bz = idx >> 8;
        int rem = idx & 255;
        m0 = (rem >> 3) * 128;
        n0 = (rem & 7) * 128;
        A = ht + (size_t)bz * NH; ldA = CCH;
        B = w;                    ldB = CCH;
        outp = qk + (size_t)bz * NQK; ldD = 1024;
    } else {
        int idx = blockIdx.x - 512;
        bz = idx >> 7;
        int rem = idx & 127;
        m0 = (rem >> 5) * 128;
        n0 = (rem & 31) * 128;
        A = wpv;                  ldA = CCH;
        B = ht + (size_t)bz * NH; ldB = CCH;
        outp = wv16 + (size_t)bz * NH; ldD = NPX;
    }

    GEMM2_MAINLOOP()

    int r4 = lane >> 2;
    int c2 = lane & 3;

    #pragma unroll
    for (int mi = 0; mi < 4; mi++) {
        #pragma unroll
        for (int half = 0; half < 2; half++) {
            int m = m0 + wm * 64 + mi * 16 + half * 8 + r4;
            float brow = isQK ? 0.f : bpv[m];
            #pragma unroll
            for (int ni = 0; ni < 4; ni++) {
                int n = n0 + wn * 32 + ni * 8 + c2 * 2;
                float v0 = acc[mi][ni][half * 2 + 0] + brow;
                float v1 = acc[mi][ni][half * 2 + 1] + brow;
                if (isQK) { v0 += bqk[n]; v1 += bqk[n + 1]; }
                *(uint32_t*)(outp + (size_t)m * ldD + n) = pack2(__float2half(v0), __float2half(v1));
            }
        }
    }
}

// ---- scores GEMM (big tiles): E=exp(scale*s) fp16 + per-row partial sums ----
__global__ void gemm_scores(
    const fp16* __restrict__ A, int ldA, size_t strideA,
    const fp16* __restrict__ B, int ldB, size_t strideB,
    int K,
    fp16* __restrict__ outE, int ldD, size_t strideD,
    float scale)
{
    extern __shared__ char smemraw[];
    int tid = threadIdx.x, wid = tid >> 5, lane = tid & 31;
    int m0 = blockIdx.y * 128, n0 = blockIdx.x * 256, bz = blockIdx.z;
    A += (size_t)bz * strideA;
    B += (size_t)bz * strideB;

    GEMM_MAINLOOP()

    int r4 = lane >> 2;
    int c2 = lane & 3;
    fp16* oh = outE + (size_t)bz * strideD;
    float rsum[8];
    #pragma unroll
    for (int r = 0; r < 8; r++) rsum[r] = 0.f;

    #pragma unroll
    for (int mi = 0; mi < 4; mi++) {
        #pragma unroll
        for (int half = 0; half < 2; half++) {
            int m = m0 + wm * 64 + mi * 16 + half * 8 + r4;
            float rs = 0.f;
            #pragma unroll
            for (int ni = 0; ni < 8; ni++) {
                int n = n0 + wn * 64 + ni * 8 + c2 * 2;
                float e0 = __expf(acc[mi][ni][half * 2 + 0] * scale);
                float e1 = __expf(acc[mi][ni][half * 2 + 1] * scale);
                *(uint32_t*)(oh + (size_t)m * ldD + n) = pack2(__float2half(e0), __float2half(e1));
                rs += e0 + e1;
            }
            rsum[mi * 2 + half] = rs;
        }
    }
    #pragma unroll
    for (int r = 0; r < 8; r++) {
        rsum[r] += __shfl_xor_sync(0xffffffffu, rsum[r], 1);
        rsum[r] += __shfl_xor_sync(0xffffffffu, rsum[r], 2);
    }
    __syncthreads();
    float* sp = (float*)smemraw;
    if (c2 == 0) {
        #pragma unroll
        for (int mi = 0; mi < 4; mi++)
            #pragma unroll
            for (int half = 0; half < 2; half++) {
                int rl = wm * 64 + mi * 16 + half * 8 + r4;
                sp[rl * 4 + wn] = rsum[mi * 2 + half];
            }
    }
    __syncthreads();
    if (tid < 128) {
        float s = sp[tid * 4] + sp[tid * 4 + 1] + sp[tid * 4 + 2] + sp[tid * 4 + 3];
        g_part[((size_t)bz * NPX + m0 + tid) * 16 + blockIdx.x] = s;
    }
}

// ---- final GEMM (mid tiles, grid 256): out = (WpV @ E^T) * inv_rowsum + bias + resid ----
// idx: bz=idx>>7; rem=idx&127; m0=(rem>>5)*128; n0=(rem&31)*128
__global__ void __launch_bounds__(256, 2) gemm_final(
    const fp16* __restrict__ Ain, const fp16* __restrict__ Bin,
    float* __restrict__ outF32,
    const float* __restrict__ biasRow,
    const float* __restrict__ resid)
{
    extern __shared__ char smemraw[];
    int tid = threadIdx.x, wid = tid >> 5, lane = tid & 31;
    const int K = NPX;
    int bz = blockIdx.x >> 7;
    int rem = blockIdx.x & 127;
    int m0 = (rem >> 5) * 128;
    int n0 = (rem & 31) * 128;
    const fp16* A = Ain + (size_t)bz * NH;  int ldA = NPX;
    const fp16* B = Bin + (size_t)bz * NN;  int ldB = NPX;

    GEMM2_MAINLOOP()

    // inverse row sums for this CTA's 128 columns
    float* sp = (float*)smemraw;
    if (tid < 128) {
        const float* p = g_part + ((size_t)bz * NPX + n0 + tid) * 16;
        float s = 0.f;
        #pragma unroll
        for (int k = 0; k < 16; k++) s += p[k];
        sp[tid] = 1.0f / s;
    }
    __syncthreads();

    int r4 = lane >> 2;
    int c2 = lane & 3;
    float* of = outF32 + (size_t)bz * CCH * NPX;
    const float* rp = resid + (size_t)bz * CCH * NPX;

    #pragma unroll
    for (int mi = 0; mi < 4; mi++) {
        #pragma unroll
        for (int half = 0; half < 2; half++) {
            int m = m0 + wm * 64 + mi * 16 + half * 8 + r4;
            float brow = biasRow[m];
            #pragma unroll
            for (int ni = 0; ni < 4; ni++) {
                int n = n0 + wn * 32 + ni * 8 + c2 * 2;
                float v0 = acc[mi][ni][half * 2 + 0] * sp[n - n0]     + brow;
                float v1 = acc[mi][ni][half * 2 + 1] * sp[n + 1 - n0] + brow;
                size_t off = (size_t)m * NPX + n;
                float2 q = *(const float2*)(rp + off);
                v0 += q.x; v1 += q.y;
                *(float2*)(of + off) = make_float2(v0, v1);
            }
        }
    }
}

// ---------------- launch ----------------
extern "C" void kernel_launch(void* const* d_in, const int* in_sizes, int n_in,
                              void* d_out, int out_size) {
    const float* x     = (const float*)d_in[0];
    const float* gamma = (const float*)d_in[1];
    const float* beta  = (const float*)d_in[2];
    const float* wq    = (const float*)d_in[3];
    const float* bq    = (const float*)d_in[4];
    const float* wk    = (const float*)d_in[5];
    const float* bk    = (const float*)d_in[6];
    const float* wv    = (const float*)d_in[7];
    const float* bv    = (const float*)d_in[8];
    const float* wp    = (const float*)d_in[9];
    const float* bp    = (const float*)d_in[10];
    float* out = (float*)d_out;

    fp16 *ht, *w, *wvT, *wpv, *qk, *wv16, *E;
    float *bqk, *bpv;
    cudaGetSymbolAddress((void**)&ht, g_ht);
    cudaGetSymbolAddress((void**)&w, g_w);
    cudaGetSymbolAddress((void**)&wvT, g_wvT);
    cudaGetSymbolAddress((void**)&wpv, g_wpv);
    cudaGetSymbolAddress((void**)&qk, g_qk);
    cudaGetSymbolAddress((void**)&wv16, g_wv16);
    cudaGetSymbolAddress((void**)&E, g_E);
    cudaGetSymbolAddress((void**)&bqk, g_bqk);
    cudaGetSymbolAddress((void**)&bpv, g_bpv);

    const int SMEM_DYN  = 3 * STG;      // 162 KB (scores)
    const int SMEM_MID  = 2 * T2STG;    // 73.7 KB (qkwpv, final)
    const int SMEM_WPV  = 3 * SSTG;     // 55 KB
    cudaFuncSetAttribute(gemm_qkwpv, cudaFuncAttributeMaxDynamicSharedMemorySize, SMEM_MID);
    cudaFuncSetAttribute(gemm_scores, cudaFuncAttributeMaxDynamicSharedMemorySize, SMEM_DYN);
    cudaFuncSetAttribute(gemm_final, cudaFuncAttributeMaxDynamicSharedMemorySize, SMEM_MID);
    cudaFuncSetAttribute(wpv_gemm, cudaFuncAttributeMaxDynamicSharedMemorySize, SMEM_WPV);

    // fused prep (gn first)
    prep_all<<<4484, 256>>>(wq, wk, wv, wp, bq, bk, bv, x, gamma, beta);

    // Wpv = wp @ wv : [512,512] fp16, 64 CTAs
    wpv_gemm<<<64, 256, SMEM_WPV>>>(w + 3 * WS, wvT, wpv);

    // merged QK + WpV : 768 mid-tile CTAs, 2 CTAs/SM
    gemm_qkwpv<<<768, 256, SMEM_MID>>>(ht, w, wpv, qk, wv16, bqk, bpv);

    // scores -> E = exp(scale * Q@K^T) fp16 + partial sums
    const float scale = 1.0f / sqrtf((float)CCH);
    gemm_scores<<<dim3(NPX / 256, NPX / 128, 2), 256, SMEM_DYN>>>(
        qk, 1024, NQK, qk + 512, 1024, NQK, CCH,
        E, NPX, NN, scale);

    // final: 256 mid-tile CTAs, 2 CTAs/SM
    gemm_final<<<256, 256, SMEM_MID>>>(wv16, E, out, bp, x);
}

// round 15
// speedup vs baseline: 1.0890x; 1.0057x over previous
#include <cuda_runtime.h>
#include <cuda_fp16.h>
#include <math.h>
#include <stdint.h>

#define CCH 512
#define NPX 4096
typedef __half fp16;

static const size_t NH  = (size_t)NPX * CCH;
static const size_t NN  = (size_t)NPX * NPX;
static const size_t NQK = (size_t)NPX * 1024;
#define WS ((size_t)CCH * CCH)

// ---------------- static scratch ----------------
__device__ fp16  g_ht[(size_t)2 * NPX * CCH];    // GN output [B][N][C]
__device__ fp16  g_w[(size_t)4 * CCH * CCH];     // wq,wk,wv,wp fp16
__device__ fp16  g_wvT[(size_t)CCH * CCH];       // wv^T fp16
__device__ fp16  g_wpv[(size_t)CCH * CCH];       // Wpv = wp@wv fp16
__device__ float g_bpv[CCH];                     // wp@bv
__device__ float g_bqk[1024];                    // concat bq|bk
__device__ fp16  g_qk[(size_t)2 * NPX * 1024];   // [B][N][1024]: Q|K
__device__ fp16  g_wv16[(size_t)2 * CCH * NPX];  // WpV [B][C][N]
__device__ fp16  g_E[(size_t)2 * NPX * NPX];     // exp(scores) fp16
__device__ float g_part[(size_t)2 * NPX * 32];   // per-(row, nblock) partial sums

// ---------------- helpers ----------------
__device__ __forceinline__ uint32_t smem_u32(const void* p) {
    uint32_t a;
    asm("{ .reg .u64 t; cvta.to.shared.u64 t, %1; cvt.u32.u64 %0, t; }" : "=r"(a) : "l"(p));
    return a;
}
__device__ __forceinline__ uint32_t pack2(fp16 a, fp16 b) {
    __half2 t; t.x = a; t.y = b;
    return *reinterpret_cast<uint32_t*>(&t);
}
__device__ __forceinline__ void cp16(uint32_t s, const void* g) {
    asm volatile("cp.async.cg.shared.global [%0], [%1], 16;" :: "r"(s), "l"(g));
}
__device__ __forceinline__ void ldsm4(uint32_t* r, uint32_t addr) {
    asm volatile("ldmatrix.sync.aligned.m8n8.x4.shared.b16 {%0,%1,%2,%3}, [%4];"
        : "=r"(r[0]), "=r"(r[1]), "=r"(r[2]), "=r"(r[3]) : "r"(addr));
}
__device__ __forceinline__ void mma16816(float* d, const uint32_t* a, uint32_t b0, uint32_t b1) {
    asm volatile("mma.sync.aligned.m16n8k16.row.col.f32.f16.f16.f32 "
        "{%0,%1,%2,%3}, {%4,%5,%6,%7}, {%8,%9}, {%0,%1,%2,%3};"
        : "+f"(d[0]), "+f"(d[1]), "+f"(d[2]), "+f"(d[3])
        : "r"(a[0]), "r"(a[1]), "r"(a[2]), "r"(a[3]), "r"(b0), "r"(b1));
}

// ---------------- fused prep: GroupNorm FIRST, then wconv + wvT + bqk + bpv ----------------
__global__ void __launch_bounds__(256) prep_all(const float* __restrict__ wq,
                                                const float* __restrict__ wk,
                                                const float* __restrict__ wv,
                                                const float* __restrict__ wp,
                                                const float* __restrict__ bq,
                                                const float* __restrict__ bk,
                                                const float* __restrict__ bv,
                                                const float* __restrict__ x,
                                                const float* __restrict__ gamma,
                                                const float* __restrict__ beta) {
    int bid = blockIdx.x;
    int tid = threadIdx.x;
    if (bid < 64) {
        // ---- GroupNorm ----
        int b = bid >> 5;
        int g = bid & 31;
        const size_t base = ((size_t)b * CCH + (size_t)g * 16) * NPX;
        const float4* xp = (const float4*)(x + base);
        const int TOT4 = 16 * NPX / 4;

        float s = 0.f, ss = 0.f;
        for (int i = tid; i < TOT4; i += 256) {
            float4 v = xp[i];
            s  += v.x + v.y + v.z + v.w;
            ss += v.x * v.x + v.y * v.y + v.z * v.z + v.w * v.w;
        }
        __shared__ float rs[8], rss[8];
        #pragma unroll
        for (int o = 16; o > 0; o >>= 1) {
            s  += __shfl_xor_sync(0xffffffffu, s, o);
            ss += __shfl_xor_sync(0xffffffffu, ss, o);
        }
        if ((tid & 31) == 0) { rs[tid >> 5] = s; rss[tid >> 5] = ss; }
        __syncthreads();
        float S = 0.f, SS = 0.f;
        #pragma unroll
        for (int w = 0; w < 8; w++) { S += rs[w]; SS += rss[w]; }
        const float inv_cnt = 1.0f / (float)(16 * NPX);
        float mean = S * inv_cnt;
        float var  = SS * inv_cnt - mean * mean;
        float rstd = rsqrtf(var + 1e-6f);

        __shared__ float sga[16], sbe[16];
        if (tid < 16) {
            int c = g * 16 + tid;
            float ga = gamma[c] * rstd;
            sga[tid] = ga;
            sbe[tid] = beta[c] - mean * ga;
        }
        __shared__ float xs[16][256];
        __syncthreads();

        for (int p0 = 0; p0 < NPX; p0 += 256) {
            #pragma unroll
            for (int c = 0; c < 16; c++) xs[c][tid] = x[base + (size_t)c * NPX + p0 + tid];
            __syncthreads();
            uint32_t hw[8];
            #pragma unroll
            for (int c2 = 0; c2 < 8; c2++) {
                float v0 = xs[2 * c2][tid]     * sga[2 * c2]     + sbe[2 * c2];
                float v1 = xs[2 * c2 + 1][tid] * sga[2 * c2 + 1] + sbe[2 * c2 + 1];
                hw[c2] = pack2(__float2half(v0), __float2half(v1));
            }
            size_t o = ((size_t)b * NPX + p0 + tid) * CCH + g * 16;
            ((uint4*)(g_ht + o))[0] = make_uint4(hw[0], hw[1], hw[2], hw[3]);
            ((uint4*)(g_ht + o))[1] = make_uint4(hw[4], hw[5], hw[6], hw[7]);
            __syncthreads();
        }
        return;
    }
    if (bid < 4160) {
        size_t i = (size_t)(bid - 64) * 256 + tid;
        size_t which = i / WS, r = i - which * WS;
        const float* w = (which == 0) ? wq : (which == 1) ? wk : (which == 2) ? wv : wp;
        g_w[i] = __float2half(w[r]);
        return;
    }
    if (bid < 4416) {
        int t = bid - 4160;
        int bx = (t & 15) * 32, by = (t >> 4) * 32;
        int tx = tid & 31, ty = tid >> 5;    // 32 x 8
        __shared__ fp16 sm[32][33];
        #pragma unroll
        for (int r = 0; r < 32; r += 8)
            sm[ty + r][tx] = __float2half(wv[(size_t)(by + ty + r) * CCH + bx + tx]);
        __syncthreads();
        #pragma unroll
        for (int r = 0; r < 32; r += 8)
            g_wvT[(size_t)(bx + ty + r) * CCH + by + tx] = sm[tx][ty + r];
        return;
    }
    if (bid < 4420) {
        int i = (bid - 4416) * 256 + tid;
        g_bqk[i] = (i < 512) ? bq[i] : bk[i - 512];
        return;
    }
    {
        int wid = tid >> 5, lane = tid & 31;
        int c = (bid - 4420) * 8 + wid;
        const float* row = wp + (size_t)c * CCH;
        float s = 0.f;
        #pragma unroll
        for (int j = 0; j < 16; j++) s += row[lane + j * 32] * bv[lane + j * 32];
        #pragma unroll
        for (int o = 16; o > 0; o >>= 1) s += __shfl_xor_sync(0xffffffffu, s, o);
        if (lane == 0) g_bpv[c] = s;
    }
}

// ---------------- small GEMM: Wpv = wp @ wv  (512x512x512), CTA 64x64, grid 64 ----------------
#define SROWB 144
#define SSTG_A (64 * SROWB)
#define SSTG   (2 * SSTG_A)
__global__ void __launch_bounds__(256) wpv_gemm(const fp16* __restrict__ A,
                                                const fp16* __restrict__ B,
                                                fp16* __restrict__ D) {
    extern __shared__ char smemraw[];
    int tid = threadIdx.x, wid = tid >> 5, lane = tid & 31;
    int m0 = (blockIdx.x >> 3) * 64, n0 = (blockIdx.x & 7) * 64;
    uint32_t base = smem_u32(smemraw);
    int wm = wid & 1, wn = wid >> 1;

    float acc[2][2][4];
    #pragma unroll
    for (int a = 0; a < 2; a++)
        #pragma unroll
        for (int b = 0; b < 2; b++)
            #pragma unroll
            for (int c = 0; c < 4; c++) acc[a][b][c] = 0.f;

    auto load_chunk = [&](int i) {
        int st = i % 3;
        size_t kb = (size_t)i * 64;
        uint32_t sa = base + st * SSTG;
        uint32_t sb = sa + SSTG_A;
        #pragma unroll
        for (int r = 0; r < 2; r++) {
            int u = tid + r * 256;
            int row = u >> 3, cs = u & 7;
            cp16(sa + (uint32_t)(row * SROWB + cs * 16),
                 A + (size_t)(m0 + row) * CCH + kb + cs * 8);
            cp16(sb + (uint32_t)(row * SROWB + cs * 16),
                 B + (size_t)(n0 + row) * CCH + kb + cs * 8);
        }
    };

    load_chunk(0);
    asm volatile("cp.async.commit_group;" ::: "memory");
    load_chunk(1);
    asm volatile("cp.async.commit_group;" ::: "memory");

    uint32_t a_off[2], b_off;
    #pragma unroll
    for (int mi = 0; mi < 2; mi++) {
        int row = wm * 32 + mi * 16 + (lane & 15);
        a_off[mi] = (uint32_t)(row * SROWB + ((lane >> 4) * 8) * 2);
    }
    {
        int row = wn * 16 + ((lane >> 4) << 3) + (lane & 7);
        b_off = (uint32_t)(row * SROWB + ((((lane >> 3) & 1) << 3)) * 2);
    }

    const int nch = 8;
    for (int i = 0; i < nch; i++) {
        if (i < nch - 1) asm volatile("cp.async.wait_group 1;" ::: "memory");
        else             asm volatile("cp.async.wait_group 0;" ::: "memory");
        __syncthreads();
        if (i + 2 < nch) {
            load_chunk(i + 2);
            asm volatile("cp.async.commit_group;" ::: "memory");
        }
        uint32_t sa = base + (i % 3) * SSTG;
        uint32_t sb = sa + SSTG_A;

        #pragma unroll
        for (int kk = 0; kk < 4; kk++) {
            uint32_t ko = (uint32_t)(kk * 32);
            uint32_t afr[2][4], bfr[4];
            #pragma unroll
            for (int mi = 0; mi < 2; mi++) ldsm4(afr[mi], sa + a_off[mi] + ko);
            ldsm4(bfr, sb + b_off + ko);
            #pragma unroll
            for (int mi = 0; mi < 2; mi++)
                #pragma unroll
                for (int ni = 0; ni < 2; ni++)
                    mma16816(acc[mi][ni], afr[mi], bfr[ni * 2], bfr[ni * 2 + 1]);
        }
        __syncthreads();
    }

    int r4 = lane >> 2;
    int c2 = lane & 3;
    #pragma unroll
    for (int mi = 0; mi < 2; mi++)
        #pragma unroll
        for (int half = 0; half < 2; half++) {
            int m = m0 + wm * 32 + mi * 16 + half * 8 + r4;
            #pragma unroll
            for (int ni = 0; ni < 2; ni++) {
                int n = n0 + wn * 16 + ni * 8 + c2 * 2;
                *(uint32_t*)(D + (size_t)m * CCH + n) =
                    pack2(__float2half(acc[mi][ni][half * 2 + 0]),
                          __float2half(acc[mi][ni][half * 2 + 1]));
            }
        }
}

// ================= mid-tile GEMM: CTA 128x128, warp 64x32, 2-stage, 2 CTAs/SM =================
#define ROWB   144
#define T2STG_A (128 * ROWB)        // 18432
#define T2STG   (2 * T2STG_A)       // 36864 per stage; x2 stages = 73728

#define GEMM2_MAINLOOP() \
    uint32_t base = smem_u32(smemraw); \
    int wm = wid & 1, wn = wid >> 1; \
    const int nch = K >> 6; \
    float acc[4][4][4]; \
    _Pragma("unroll") \
    for (int a_ = 0; a_ < 4; a_++) \
        _Pragma("unroll") \
        for (int b_ = 0; b_ < 4; b_++) \
            _Pragma("unroll") \
            for (int c_ = 0; c_ < 4; c_++) acc[a_][b_][c_] = 0.f; \
    auto load_chunk = [&](int i) { \
        int st = i & 1; \
        size_t kb = (size_t)i * 64; \
        uint32_t sa = base + st * T2STG; \
        uint32_t sb = sa + T2STG_A; \
        _Pragma("unroll") \
        for (int r = 0; r < 4; r++) { \
            int u = tid + r * 256; \
            int row = u >> 3, cs = u & 7; \
            cp16(sa + (uint32_t)(row * ROWB + cs * 16), \
                 A + (size_t)(m0 + row) * ldA + kb + cs * 8); \
            cp16(sb + (uint32_t)(row * ROWB + cs * 16), \
                 B + (size_t)(n0 + row) * ldB + kb + cs * 8); \
        } \
    }; \
    load_chunk(0); \
    asm volatile("cp.async.commit_group;" ::: "memory"); \
    uint32_t a_off[4], b_off[2]; \
    _Pragma("unroll") \
    for (int mi = 0; mi < 4; mi++) { \
        int row = wm * 64 + mi * 16 + (lane & 15); \
        a_off[mi] = (uint32_t)(row * ROWB + ((lane >> 4) * 8) * 2); \
    } \
    _Pragma("unroll") \
    for (int nb = 0; nb < 2; nb++) { \
        int row = wn * 32 + nb * 16 + ((lane >> 4) << 3) + (lane & 7); \
        b_off[nb] = (uint32_t)(row * ROWB + ((((lane >> 3) & 1) << 3)) * 2); \
    } \
    for (int i = 0; i < nch; i++) { \
        if (i + 1 < nch) { \
            load_chunk(i + 1); \
            asm volatile("cp.async.commit_group;" ::: "memory"); \
            asm volatile("cp.async.wait_group 1;" ::: "memory"); \
        } else { \
            asm volatile("cp.async.wait_group 0;" ::: "memory"); \
        } \
        __syncthreads(); \
        uint32_t sa = base + (i & 1) * T2STG; \
        uint32_t sb = sa + T2STG_A; \
        uint32_t afr[2][4][4], bfr[2][2][4]; \
        _Pragma("unroll") \
        for (int mi = 0; mi < 4; mi++) ldsm4(afr[0][mi], sa + a_off[mi]); \
        _Pragma("unroll") \
        for (int nb = 0; nb < 2; nb++) ldsm4(bfr[0][nb], sb + b_off[nb]); \
        _Pragma("unroll") \
        for (int kk = 0; kk < 4; kk++) { \
            int cur = kk & 1, nxt = cur ^ 1; \
            if (kk < 3) { \
                uint32_t ko = (uint32_t)((kk + 1) * 32); \
                _Pragma("unroll") \
                for (int mi = 0; mi < 4; mi++) ldsm4(afr[nxt][mi], sa + a_off[mi] + ko); \
                _Pragma("unroll") \
                for (int nb = 0; nb < 2; nb++) ldsm4(bfr[nxt][nb], sb + b_off[nb] + ko); \
            } \
            _Pragma("unroll") \
            for (int mi = 0; mi < 4; mi++) \
                _Pragma("unroll") \
                for (int ni = 0; ni < 4; ni++) \
                    mma16816(acc[mi][ni], afr[cur][mi], \
                             bfr[cur][ni >> 1][(ni & 1) * 2], bfr[cur][ni >> 1][(ni & 1) * 2 + 1]); \
        } \
        __syncthreads(); \
    }

// ---- merged QK + WpV GEMM (mid tiles, 768 blocks) ----
__global__ void __launch_bounds__(256, 2) gemm_qkwpv(const fp16* __restrict__ ht,
                                                     const fp16* __restrict__ w,
                                                     const fp16* __restrict__ wpv,
                                                     fp16* __restrict__ qk,
                                                     fp16* __restrict__ wv16,
                                                     const float* __restrict__ bqk,
                                                     const float* __restrict__ bpv)
{
    extern __shared__ char smemraw[];
    int tid = threadIdx.x, wid = tid >> 5, lane = tid & 31;
    const int K = 512;

    const fp16 *A, *B;
    int ldA, ldB, m0, n0;
    bool isQK = (blockIdx.x < 512);
    int bz;
    fp16* outp;
    int ldD;
    if (isQK) {
        int idx = blockIdx.x;
        bz = idx >> 8;
        int rem = idx & 255;
        m0 = (rem >> 3) * 128;
        n0 = (rem & 7) * 128;
        A = ht + (size_t)bz * NH; ldA = CCH;
        B = w;                    ldB = CCH;
        outp = qk + (size_t)bz * NQK; ldD = 1024;
    } else {
        int idx = blockIdx.x - 512;
        bz = idx >> 7;
        int rem = idx & 127;
        m0 = (rem >> 5) * 128;
        n0 = (rem & 31) * 128;
        A = wpv;                  ldA = CCH;
        B = ht + (size_t)bz * NH; ldB = CCH;
        outp = wv16 + (size_t)bz * NH; ldD = NPX;
    }

    GEMM2_MAINLOOP()

    int r4 = lane >> 2;
    int c2 = lane & 3;

    #pragma unroll
    for (int mi = 0; mi < 4; mi++) {
        #pragma unroll
        for (int half = 0; half < 2; half++) {
            int m = m0 + wm * 64 + mi * 16 + half * 8 + r4;
            float brow = isQK ? 0.f : bpv[m];
            #pragma unroll
            for (int ni = 0; ni < 4; ni++) {
                int n = n0 + wn * 32 + ni * 8 + c2 * 2;
                float v0 = acc[mi][ni][half * 2 + 0] + brow;
                float v1 = acc[mi][ni][half * 2 + 1] + brow;
                if (isQK) { v0 += bqk[n]; v1 += bqk[n + 1]; }
                *(uint32_t*)(outp + (size_t)m * ldD + n) = pack2(__float2half(v0), __float2half(v1));
            }
        }
    }
}

// ---- scores GEMM (mid tiles, grid 32x32x2, 2 CTAs/SM): E=exp(scale*s) + 32 partials/row ----
__global__ void __launch_bounds__(256, 2) gemm_scores(
    const fp16* __restrict__ Ain, const fp16* __restrict__ Bin,
    fp16* __restrict__ outE,
    float scale)
{
    extern __shared__ char smemraw[];
    int tid = threadIdx.x, wid = tid >> 5, lane = tid & 31;
    const int K = CCH;
    int m0 = blockIdx.y * 128, n0 = blockIdx.x * 128, bz = blockIdx.z;
    const fp16* A = Ain + (size_t)bz * NQK;  int ldA = 1024;
    const fp16* B = Bin + (size_t)bz * NQK;  int ldB = 1024;

    GEMM2_MAINLOOP()

    int r4 = lane >> 2;
    int c2 = lane & 3;
    fp16* oh = outE + (size_t)bz * NN;
    float rsum[8];
    #pragma unroll
    for (int r = 0; r < 8; r++) rsum[r] = 0.f;

    #pragma unroll
    for (int mi = 0; mi < 4; mi++) {
        #pragma unroll
        for (int half = 0; half < 2; half++) {
            int m = m0 + wm * 64 + mi * 16 + half * 8 + r4;
            float rs = 0.f;
            #pragma unroll
            for (int ni = 0; ni < 4; ni++) {
                int n = n0 + wn * 32 + ni * 8 + c2 * 2;
                float e0 = __expf(acc[mi][ni][half * 2 + 0] * scale);
                float e1 = __expf(acc[mi][ni][half * 2 + 1] * scale);
                *(uint32_t*)(oh + (size_t)m * NPX + n) = pack2(__float2half(e0), __float2half(e1));
                rs += e0 + e1;
            }
            rsum[mi * 2 + half] = rs;
        }
    }
    #pragma unroll
    for (int r = 0; r < 8; r++) {
        rsum[r] += __shfl_xor_sync(0xffffffffu, rsum[r], 1);
        rsum[r] += __shfl_xor_sync(0xffffffffu, rsum[r], 2);
    }
    __syncthreads();
    float* sp = (float*)smemraw;    // [128 rows][4 wn]
    if (c2 == 0) {
        #pragma unroll
        for (int mi = 0; mi < 4; mi++)
            #pragma unroll
            for (int half = 0; half < 2; half++) {
                int rl = wm * 64 + mi * 16 + half * 8 + r4;
                sp[rl * 4 + wn] = rsum[mi * 2 + half];
            }
    }
    __syncthreads();
    if (tid < 128) {
        float s = sp[tid * 4] + sp[tid * 4 + 1] + sp[tid * 4 + 2] + sp[tid * 4 + 3];
        g_part[((size_t)bz * NPX + m0 + tid) * 32 + blockIdx.x] = s;
    }
}

// ---- final GEMM (mid tiles, grid 256): out = (WpV @ E^T) * inv_rowsum + bias + resid ----
__global__ void __launch_bounds__(256, 2) gemm_final(
    const fp16* __restrict__ Ain, const fp16* __restrict__ Bin,
    float* __restrict__ outF32,
    const float* __restrict__ biasRow,
    const float* __restrict__ resid)
{
    extern __shared__ char smemraw[];
    int tid = threadIdx.x, wid = tid >> 5, lane = tid & 31;
    const int K = NPX;
    int bz = blockIdx.x >> 7;
    int rem = blockIdx.x & 127;
    int m0 = (rem >> 5) * 128;
    int n0 = (rem & 31) * 128;
    const fp16* A = Ain + (size_t)bz * NH;  int ldA = NPX;
    const fp16* B = Bin + (size_t)bz * NN;  int ldB = NPX;

    GEMM2_MAINLOOP()

    // inverse row sums for this CTA's 128 columns (32 partials each)
    float* sp = (float*)smemraw;
    if (tid < 128) {
        const float* p = g_part + ((size_t)bz * NPX + n0 + tid) * 32;
        float s = 0.f;
        #pragma unroll
        for (int k = 0; k < 32; k++) s += p[k];
        sp[tid] = 1.0f / s;
    }
    __syncthreads();

    int r4 = lane >> 2;
    int c2 = lane & 3;
    float* of = outF32 + (size_t)bz * CCH * NPX;
    const float* rp = resid + (size_t)bz * CCH * NPX;

    #pragma unroll
    for (int mi = 0; mi < 4; mi++) {
        #pragma unroll
        for (int half = 0; half < 2; half++) {
            int m = m0 + wm * 64 + mi * 16 + half * 8 + r4;
            float brow = biasRow[m];
            #pragma unroll
            for (int ni = 0; ni < 4; ni++) {
                int n = n0 + wn * 32 + ni * 8 + c2 * 2;
                float v0 = acc[mi][ni][half * 2 + 0] * sp[n - n0]     + brow;
                float v1 = acc[mi][ni][half * 2 + 1] * sp[n + 1 - n0] + brow;
                size_t off = (size_t)m * NPX + n;
                float2 q = *(const float2*)(rp + off);
                v0 += q.x; v1 += q.y;
                *(float2*)(of + off) = make_float2(v0, v1);
            }
        }
    }
}

// ---------------- launch ----------------
extern "C" void kernel_launch(void* const* d_in, const int* in_sizes, int n_in,
                              void* d_out, int out_size) {
    const float* x     = (const float*)d_in[0];
    const float* gamma = (const float*)d_in[1];
    const float* beta  = (const float*)d_in[2];
    const float* wq    = (const float*)d_in[3];
    const float* bq    = (const float*)d_in[4];
    const float* wk    = (const float*)d_in[5];
    const float* bk    = (const float*)d_in[6];
    const float* wv    = (const float*)d_in[7];
    const float* bv    = (const float*)d_in[8];
    const float* wp    = (const float*)d_in[9];
    const float* bp    = (const float*)d_in[10];
    float* out = (float*)d_out;

    fp16 *ht, *w, *wvT, *wpv, *qk, *wv16, *E;
    float *bqk, *bpv;
    cudaGetSymbolAddress((void**)&ht, g_ht);
    cudaGetSymbolAddress((void**)&w, g_w);
    cudaGetSymbolAddress((void**)&wvT, g_wvT);
    cudaGetSymbolAddress((void**)&wpv, g_wpv);
    cudaGetSymbolAddress((void**)&qk, g_qk);
    cudaGetSymbolAddress((void**)&wv16, g_wv16);
    cudaGetSymbolAddress((void**)&E, g_E);
    cudaGetSymbolAddress((void**)&bqk, g_bqk);
    cudaGetSymbolAddress((void**)&bpv, g_bpv);

    const int SMEM_MID = 2 * T2STG;    // 73.7 KB
    const int SMEM_WPV = 3 * SSTG;     // 55 KB
    cudaFuncSetAttribute(gemm_qkwpv, cudaFuncAttributeMaxDynamicSharedMemorySize, SMEM_MID);
    cudaFuncSetAttribute(gemm_scores, cudaFuncAttributeMaxDynamicSharedMemorySize, SMEM_MID);
    cudaFuncSetAttribute(gemm_final, cudaFuncAttributeMaxDynamicSharedMemorySize, SMEM_MID);
    cudaFuncSetAttribute(wpv_gemm, cudaFuncAttributeMaxDynamicSharedMemorySize, SMEM_WPV);

    // fused prep (gn first)
    prep_all<<<4484, 256>>>(wq, wk, wv, wp, bq, bk, bv, x, gamma, beta);

    // Wpv = wp @ wv : [512,512] fp16, 64 CTAs
    wpv_gemm<<<64, 256, SMEM_WPV>>>(w + 3 * WS, wvT, wpv);

    // merged QK + WpV : 768 mid-tile CTAs, 2 CTAs/SM
    gemm_qkwpv<<<768, 256, SMEM_MID>>>(ht, w, wpv, qk, wv16, bqk, bpv);

    // scores -> E = exp(scale * Q@K^T) fp16 + 32 partials/row  (mid tiles, 2 CTAs/SM)
    const float scale = 1.0f / sqrtf((float)CCH);
    gemm_scores<<<dim3(32, 32, 2), 256, SMEM_MID>>>(qk, qk + 512, E, scale);

    // final: 256 mid-tile CTAs, 2 CTAs/SM
    gemm_final<<<256, 256, SMEM_MID>>>(wv16, E, out, bp, x);
}

// round 17
// speedup vs baseline: 1.1342x; 1.0415x over previous
#include <cuda_runtime.h>
#include <cuda_fp16.h>
#include <math.h>
#include <stdint.h>

#define CCH 512
#define NPX 4096
typedef __half fp16;

static const size_t NH  = (size_t)NPX * CCH;
static const size_t NN  = (size_t)NPX * NPX;
#define WS ((size_t)CCH * CCH)

// ---------------- static scratch ----------------
__device__ fp16  g_ht[(size_t)2 * NPX * CCH];    // GN output [B][N][C]
__device__ fp16  g_wp[(size_t)CCH * CCH];        // wp fp16 row-major
__device__ fp16  g_wvT[(size_t)CCH * CCH];       // wv^T fp16
__device__ fp16  g_wqT[(size_t)CCH * CCH];       // wq^T fp16
__device__ fp16  g_wkT[(size_t)CCH * CCH];       // wk^T fp16
__device__ fp16  g_wpv[(size_t)CCH * CCH];       // Wpv = wp@wv fp16
__device__ fp16  g_G[(size_t)CCH * CCH];         // G = wk^T@wq fp16  (G[b][a])
__device__ float g_bpv[CCH];                     // wp@bv
__device__ float g_ub[CCH];                      // wk^T@bq
__device__ fp16  g_T[(size_t)2 * NPX * CCH];     // T = ht@G^T + ub [B][N][512]
__device__ fp16  g_wv16[(size_t)2 * CCH * NPX];  // WpV [B][C][N]
__device__ fp16  g_E[(size_t)2 * NPX * NPX];     // exp(scores) fp16
__device__ float g_part[(size_t)2 * NPX * 32];   // per-(row, nblock) partial sums

// ---------------- helpers ----------------
__device__ __forceinline__ uint32_t smem_u32(const void* p) {
    uint32_t a;
    asm("{ .reg .u64 t; cvta.to.shared.u64 t, %1; cvt.u32.u64 %0, t; }" : "=r"(a) : "l"(p));
    return a;
}
__device__ __forceinline__ uint32_t pack2(fp16 a, fp16 b) {
    __half2 t; t.x = a; t.y = b;
    return *reinterpret_cast<uint32_t*>(&t);
}
__device__ __forceinline__ void cp16(uint32_t s, const void* g) {
    asm volatile("cp.async.cg.shared.global [%0], [%1], 16;" :: "r"(s), "l"(g));
}
__device__ __forceinline__ void ldsm4(uint32_t* r, uint32_t addr) {
    asm volatile("ldmatrix.sync.aligned.m8n8.x4.shared.b16 {%0,%1,%2,%3}, [%4];"
        : "=r"(r[0]), "=r"(r[1]), "=r"(r[2]), "=r"(r[3]) : "r"(addr));
}
__device__ __forceinline__ void mma16816(float* d, const uint32_t* a, uint32_t b0, uint32_t b1) {
    asm volatile("mma.sync.aligned.m16n8k16.row.col.f32.f16.f16.f32 "
        "{%0,%1,%2,%3}, {%4,%5,%6,%7}, {%8,%9}, {%0,%1,%2,%3};"
        : "+f"(d[0]), "+f"(d[1]), "+f"(d[2]), "+f"(d[3])
        : "r"(a[0]), "r"(a[1]), "r"(a[2]), "r"(a[3]), "r"(b0), "r"(b1));
}

// ---------------- fused prep ----------------
// [0,64):        GroupNorm
// [64,1088):     wp -> fp16 row-major
// [1088,1856):   transposes: wv->wvT, wq->wqT, wk->wkT
// [1856,1920):   bpv = wp@bv
// [1920,1984):   ub = wk^T@bq
__global__ void __launch_bounds__(256) prep_all(const float* __restrict__ wq,
                                                const float* __restrict__ wk,
                                                const float* __restrict__ wv,
                                                const float* __restrict__ wp,
                                                const float* __restrict__ bq,
                                                const float* __restrict__ bv,
                                                const float* __restrict__ x,
                                                const float* __restrict__ gamma,
                                                const float* __restrict__ beta) {
    int bid = blockIdx.x;
    int tid = threadIdx.x;
    if (bid < 64) {
        // ---- GroupNorm ----
        int b = bid >> 5;
        int g = bid & 31;
        const size_t base = ((size_t)b * CCH + (size_t)g * 16) * NPX;
        const float4* xp = (const float4*)(x + base);
        const int TOT4 = 16 * NPX / 4;

        float s = 0.f, ss = 0.f;
        for (int i = tid; i < TOT4; i += 256) {
            float4 v = xp[i];
            s  += v.x + v.y + v.z + v.w;
            ss += v.x * v.x + v.y * v.y + v.z * v.z + v.w * v.w;
        }
        __shared__ float rs[8], rss[8];
        #pragma unroll
        for (int o = 16; o > 0; o >>= 1) {
            s  += __shfl_xor_sync(0xffffffffu, s, o);
            ss += __shfl_xor_sync(0xffffffffu, ss, o);
        }
        if ((tid & 31) == 0) { rs[tid >> 5] = s; rss[tid >> 5] = ss; }
        __syncthreads();
        float S = 0.f, SS = 0.f;
        #pragma unroll
        for (int w = 0; w < 8; w++) { S += rs[w]; SS += rss[w]; }
        const float inv_cnt = 1.0f / (float)(16 * NPX);
        float mean = S * inv_cnt;
        float var  = SS * inv_cnt - mean * mean;
        float rstd = rsqrtf(var + 1e-6f);

        __shared__ float sga[16], sbe[16];
        if (tid < 16) {
            int c = g * 16 + tid;
            float ga = gamma[c] * rstd;
            sga[tid] = ga;
            sbe[tid] = beta[c] - mean * ga;
        }
        __shared__ float xs[16][256];
        __syncthreads();

        for (int p0 = 0; p0 < NPX; p0 += 256) {
            #pragma unroll
            for (int c = 0; c < 16; c++) xs[c][tid] = x[base + (size_t)c * NPX + p0 + tid];
            __syncthreads();
            uint32_t hw[8];
            #pragma unroll
            for (int c2 = 0; c2 < 8; c2++) {
                float v0 = xs[2 * c2][tid]     * sga[2 * c2]     + sbe[2 * c2];
                float v1 = xs[2 * c2 + 1][tid] * sga[2 * c2 + 1] + sbe[2 * c2 + 1];
                hw[c2] = pack2(__float2half(v0), __float2half(v1));
            }
            size_t o = ((size_t)b * NPX + p0 + tid) * CCH + g * 16;
            ((uint4*)(g_ht + o))[0] = make_uint4(hw[0], hw[1], hw[2], hw[3]);
            ((uint4*)(g_ht + o))[1] = make_uint4(hw[4], hw[5], hw[6], hw[7]);
            __syncthreads();
        }
        return;
    }
    if (bid < 1088) {
        size_t i = (size_t)(bid - 64) * 256 + tid;
        g_wp[i] = __float2half(wp[i]);
        return;
    }
    if (bid < 1856) {
        int t = bid - 1088;
        const float* src = (t < 256) ? wv : (t < 512) ? wq : wk;
        fp16* dst = (t < 256) ? g_wvT : (t < 512) ? g_wqT : g_wkT;
        t &= 255;
        int bx = (t & 15) * 32, by = (t >> 4) * 32;
        int tx = tid & 31, ty = tid >> 5;    // 32 x 8
        __shared__ fp16 sm[32][33];
        #pragma unroll
        for (int r = 0; r < 32; r += 8)
            sm[ty + r][tx] = __float2half(src[(size_t)(by + ty + r) * CCH + bx + tx]);
        __syncthreads();
        #pragma unroll
        for (int r = 0; r < 32; r += 8)
            dst[(size_t)(bx + ty + r) * CCH + by + tx] = sm[tx][ty + r];
        return;
    }
    if (bid < 1920) {
        int wid = tid >> 5, lane = tid & 31;
        int c = (bid - 1856) * 8 + wid;
        const float* row = wp + (size_t)c * CCH;
        float s = 0.f;
        #pragma unroll
        for (int j = 0; j < 16; j++) s += row[lane + j * 32] * bv[lane + j * 32];
        #pragma unroll
        for (int o = 16; o > 0; o >>= 1) s += __shfl_xor_sync(0xffffffffu, s, o);
        if (lane == 0) g_bpv[c] = s;
        return;
    }
    {
        // ub[b] = sum_c wk[c][b] * bq[c]
        int wid = tid >> 5, lane = tid & 31;
        int b = (bid - 1920) * 8 + wid;
        float s = 0.f;
        #pragma unroll
        for (int j = 0; j < 16; j++) {
            int c = lane + j * 32;
            s += wk[(size_t)c * CCH + b] * bq[c];
        }
        #pragma unroll
        for (int o = 16; o > 0; o >>= 1) s += __shfl_xor_sync(0xffffffffu, s, o);
        if (lane == 0) g_ub[b] = s;
    }
}

// ---------------- small GEMMs: Wpv = wp@wv and G = wk^T@wq. 128 blocks, CTA 64x64 ----------------
#define SROWB 144
#define SSTG_A (64 * SROWB)
#define SSTG   (2 * SSTG_A)
__global__ void __launch_bounds__(256) small_gemms() {
    extern __shared__ char smemraw[];
    int tid = threadIdx.x, wid = tid >> 5, lane = tid & 31;
    bool isWpv = (blockIdx.x < 64);
    int t = blockIdx.x & 63;
    int m0 = (t >> 3) * 64, n0 = (t & 7) * 64;
    const fp16* A = isWpv ? g_wp  : g_wkT;
    const fp16* B = isWpv ? g_wvT : g_wqT;
    fp16* D       = isWpv ? g_wpv : g_G;
    uint32_t base = smem_u32(smemraw);
    int wm = wid & 1, wn = wid >> 1;

    float acc[2][2][4];
    #pragma unroll
    for (int a = 0; a < 2; a++)
        #pragma unroll
        for (int b = 0; b < 2; b++)
            #pragma unroll
            for (int c = 0; c < 4; c++) acc[a][b][c] = 0.f;

    auto load_chunk = [&](int i) {
        int st = i % 3;
        size_t kb = (size_t)i * 64;
        uint32_t sa = base + st * SSTG;
        uint32_t sb = sa + SSTG_A;
        #pragma unroll
        for (int r = 0; r < 2; r++) {
            int u = tid + r * 256;
            int row = u >> 3, cs = u & 7;
            cp16(sa + (uint32_t)(row * SROWB + cs * 16),
                 A + (size_t)(m0 + row) * CCH + kb + cs * 8);
            cp16(sb + (uint32_t)(row * SROWB + cs * 16),
                 B + (size_t)(n0 + row) * CCH + kb + cs * 8);
        }
    };

    load_chunk(0);
    asm volatile("cp.async.commit_group;" ::: "memory");
    load_chunk(1);
    asm volatile("cp.async.commit_group;" ::: "memory");

    uint32_t a_off[2], b_off;
    #pragma unroll
    for (int mi = 0; mi < 2; mi++) {
        int row = wm * 32 + mi * 16 + (lane & 15);
        a_off[mi] = (uint32_t)(row * SROWB + ((lane >> 4) * 8) * 2);
    }
    {
        int row = wn * 16 + ((lane >> 4) << 3) + (lane & 7);
        b_off = (uint32_t)(row * SROWB + ((((lane >> 3) & 1) << 3)) * 2);
    }

    const int nch = 8;
    for (int i = 0; i < nch; i++) {
        if (i < nch - 1) asm volatile("cp.async.wait_group 1;" ::: "memory");
        else             asm volatile("cp.async.wait_group 0;" ::: "memory");
        __syncthreads();
        if (i + 2 < nch) {
            load_chunk(i + 2);
            asm volatile("cp.async.commit_group;" ::: "memory");
        }
        uint32_t sa = base + (i % 3) * SSTG;
        uint32_t sb = sa + SSTG_A;

        #pragma unroll
        for (int kk = 0; kk < 4; kk++) {
            uint32_t ko = (uint32_t)(kk * 32);
            uint32_t afr[2][4], bfr[4];
            #pragma unroll
            for (int mi = 0; mi < 2; mi++) ldsm4(afr[mi], sa + a_off[mi] + ko);
            ldsm4(bfr, sb + b_off + ko);
            #pragma unroll
            for (int mi = 0; mi < 2; mi++)
                #pragma unroll
                for (int ni = 0; ni < 2; ni++)
                    mma16816(acc[mi][ni], afr[mi], bfr[ni * 2], bfr[ni * 2 + 1]);
        }
        __syncthreads();
    }

    int r4 = lane >> 2;
    int c2 = lane & 3;
    #pragma unroll
    for (int mi = 0; mi < 2; mi++)
        #pragma unroll
        for (int half = 0; half < 2; half++) {
            int m = m0 + wm * 32 + mi * 16 + half * 8 + r4;
            #pragma unroll
            for (int ni = 0; ni < 2; ni++) {
                int n = n0 + wn * 16 + ni * 8 + c2 * 2;
                *(uint32_t*)(D + (size_t)m * CCH + n) =
                    pack2(__float2half(acc[mi][ni][half * 2 + 0]),
                          __float2half(acc[mi][ni][half * 2 + 1]));
            }
        }
}

// ================= mid-tile GEMM: CTA 128x128, warp 64x32, 2-stage, 2 CTAs/SM =================
#define ROWB   144
#define T2STG_A (128 * ROWB)
#define T2STG   (2 * T2STG_A)

#define GEMM2_MAINLOOP() \
    uint32_t base = smem_u32(smemraw); \
    int wm = wid & 1, wn = wid >> 1; \
    const int nch = K >> 6; \
    float acc[4][4][4]; \
    _Pragma("unroll") \
    for (int a_ = 0; a_ < 4; a_++) \
        _Pragma("unroll") \
        for (int b_ = 0; b_ < 4; b_++) \
            _Pragma("unroll") \
            for (int c_ = 0; c_ < 4; c_++) acc[a_][b_][c_] = 0.f; \
    auto load_chunk = [&](int i) { \
        int st = i & 1; \
        size_t kb = (size_t)i * 64; \
        uint32_t sa = base + st * T2STG; \
        uint32_t sb = sa + T2STG_A; \
        _Pragma("unroll") \
        for (int r = 0; r < 4; r++) { \
            int u = tid + r * 256; \
            int row = u >> 3, cs = u & 7; \
            cp16(sa + (uint32_t)(row * ROWB + cs * 16), \
                 A + (size_t)(m0 + row) * ldA + kb + cs * 8); \
            cp16(sb + (uint32_t)(row * ROWB + cs * 16), \
                 B + (size_t)(n0 + row) * ldB + kb + cs * 8); \
        } \
    }; \
    load_chunk(0); \
    asm volatile("cp.async.commit_group;" ::: "memory"); \
    uint32_t a_off[4], b_off[2]; \
    _Pragma("unroll") \
    for (int mi = 0; mi < 4; mi++) { \
        int row = wm * 64 + mi * 16 + (lane & 15); \
        a_off[mi] = (uint32_t)(row * ROWB + ((lane >> 4) * 8) * 2); \
    } \
    _Pragma("unroll") \
    for (int nb = 0; nb < 2; nb++) { \
        int row = wn * 32 + nb * 16 + ((lane >> 4) << 3) + (lane & 7); \
        b_off[nb] = (uint32_t)(row * ROWB + ((((lane >> 3) & 1) << 3)) * 2); \
    } \
    for (int i = 0; i < nch; i++) { \
        if (i + 1 < nch) { \
            load_chunk(i + 1); \
            asm volatile("cp.async.commit_group;" ::: "memory"); \
            asm volatile("cp.async.wait_group 1;" ::: "memory"); \
        } else { \
            asm volatile("cp.async.wait_group 0;" ::: "memory"); \
        } \
        __syncthreads(); \
        uint32_t sa = base + (i & 1) * T2STG; \
        uint32_t sb = sa + T2STG_A; \
        uint32_t afr[2][4][4], bfr[2][2][4]; \
        _Pragma("unroll") \
        for (int mi = 0; mi < 4; mi++) ldsm4(afr[0][mi], sa + a_off[mi]); \
        _Pragma("unroll") \
        for (int nb = 0; nb < 2; nb++) ldsm4(bfr[0][nb], sb + b_off[nb]); \
        _Pragma("unroll") \
        for (int kk = 0; kk < 4; kk++) { \
            int cur = kk & 1, nxt = cur ^ 1; \
            if (kk < 3) { \
                uint32_t ko = (uint32_t)((kk + 1) * 32); \
                _Pragma("unroll") \
                for (int mi = 0; mi < 4; mi++) ldsm4(afr[nxt][mi], sa + a_off[mi] + ko); \
                _Pragma("unroll") \
                for (int nb = 0; nb < 2; nb++) ldsm4(bfr[nxt][nb], sb + b_off[nb] + ko); \
            } \
            _Pragma("unroll") \
            for (int mi = 0; mi < 4; mi++) \
                _Pragma("unroll") \
                for (int ni = 0; ni < 4; ni++) \
                    mma16816(acc[mi][ni], afr[cur][mi], \
                             bfr[cur][ni >> 1][(ni & 1) * 2], bfr[cur][ni >> 1][(ni & 1) * 2 + 1]); \
        } \
        __syncthreads(); \
    }

// ---- merged T + WpV GEMM (mid tiles, 512 blocks) ----
// blocks [0,256):  T = ht@G^T + ub : bz=idx>>7; rem=idx&127; m0=(rem>>2)*128; n0=(rem&3)*128
// blocks [256,512): WpV = Wpv@ht^T + bpv : idx2=idx-256; bz=idx2>>7; rem=idx2&127; m0=(rem>>5)*128; n0=(rem&31)*128
__global__ void __launch_bounds__(256, 2) gemm_twpv(const fp16* __restrict__ ht,
                                                    fp16* __restrict__ Tout,
                                                    fp16* __restrict__ wv16)
{
    extern __shared__ char smemraw[];
    int tid = threadIdx.x, wid = tid >> 5, lane = tid & 31;
    const int K = 512;

    const fp16 *A, *B;
    int ldA, ldB, m0, n0;
    bool isT = (blockIdx.x < 256);
    int bz;
    fp16* outp;
    int ldD;
    if (isT) {
        int idx = blockIdx.x;
        bz = idx >> 7;
        int rem = idx & 127;
        m0 = (rem >> 2) * 128;
        n0 = (rem & 3) * 128;
        A = ht + (size_t)bz * NH; ldA = CCH;
        B = g_G;                  ldB = CCH;
        outp = Tout + (size_t)bz * NH; ldD = CCH;
    } else {
        int idx = blockIdx.x - 256;
        bz = idx >> 7;
        int rem = idx & 127;
        m0 = (rem >> 5) * 128;
        n0 = (rem & 31) * 128;
        A = g_wpv;                ldA = CCH;
        B = ht + (size_t)bz * NH; ldB = CCH;
        outp = wv16 + (size_t)bz * NH; ldD = NPX;
    }

    GEMM2_MAINLOOP()

    int r4 = lane >> 2;
    int c2 = lane & 3;

    #pragma unroll
    for (int mi = 0; mi < 4; mi++) {
        #pragma unroll
        for (int half = 0; half < 2; half++) {
            int m = m0 + wm * 64 + mi * 16 + half * 8 + r4;
            float brow = isT ? 0.f : g_bpv[m];
            #pragma unroll
            for (int ni = 0; ni < 4; ni++) {
                int n = n0 + wn * 32 + ni * 8 + c2 * 2;
                float v0 = acc[mi][ni][half * 2 + 0] + brow;
                float v1 = acc[mi][ni][half * 2 + 1] + brow;
                if (isT) { v0 += g_ub[n]; v1 += g_ub[n + 1]; }
                *(uint32_t*)(outp + (size_t)m * ldD + n) = pack2(__float2half(v0), __float2half(v1));
            }
        }
    }
}

// ---- scores GEMM (mid tiles, grid 32x32x2): E=exp(scale*(T@ht^T)) + 32 partials/row ----
__global__ void __launch_bounds__(256, 2) gemm_scores(
    const fp16* __restrict__ Tin, const fp16* __restrict__ htin,
    fp16* __restrict__ outE,
    float scale)
{
    extern __shared__ char smemraw[];
    int tid = threadIdx.x, wid = tid >> 5, lane = tid & 31;
    const int K = CCH;
    int m0 = blockIdx.y * 128, n0 = blockIdx.x * 128, bz = blockIdx.z;
    const fp16* A = Tin  + (size_t)bz * NH;  int ldA = CCH;
    const fp16* B = htin + (size_t)bz * NH;  int ldB = CCH;

    GEMM2_MAINLOOP()

    int r4 = lane >> 2;
    int c2 = lane & 3;
    fp16* oh = outE + (size_t)bz * NN;
    float rsum[8];
    #pragma unroll
    for (int r = 0; r < 8; r++) rsum[r] = 0.f;

    #pragma unroll
    for (int mi = 0; mi < 4; mi++) {
        #pragma unroll
        for (int half = 0; half < 2; half++) {
            int m = m0 + wm * 64 + mi * 16 + half * 8 + r4;
            float rs = 0.f;
            #pragma unroll
            for (int ni = 0; ni < 4; ni++) {
                int n = n0 + wn * 32 + ni * 8 + c2 * 2;
                float e0 = __expf(acc[mi][ni][half * 2 + 0] * scale);
                float e1 = __expf(acc[mi][ni][half * 2 + 1] * scale);
                *(uint32_t*)(oh + (size_t)m * NPX + n) = pack2(__float2half(e0), __float2half(e1));
                rs += e0 + e1;
            }
            rsum[mi * 2 + half] = rs;
        }
    }
    #pragma unroll
    for (int r = 0; r < 8; r++) {
        rsum[r] += __shfl_xor_sync(0xffffffffu, rsum[r], 1);
        rsum[r] += __shfl_xor_sync(0xffffffffu, rsum[r], 2);
    }
    __syncthreads();
    float* sp = (float*)smemraw;
    if (c2 == 0) {
        #pragma unroll
        for (int mi = 0; mi < 4; mi++)
            #pragma unroll
            for (int half = 0; half < 2; half++) {
                int rl = wm * 64 + mi * 16 + half * 8 + r4;
                sp[rl * 4 + wn] = rsum[mi * 2 + half];
            }
    }
    __syncthreads();
    if (tid < 128) {
        float s = sp[tid * 4] + sp[tid * 4 + 1] + sp[tid * 4 + 2] + sp[tid * 4 + 3];
        g_part[((size_t)bz * NPX + m0 + tid) * 32 + blockIdx.x] = s;
    }
}

// ---- final GEMM (mid tiles, grid 256): out = (WpV @ E^T) * inv_rowsum + bias + resid ----
__global__ void __launch_bounds__(256, 2) gemm_final(
    const fp16* __restrict__ Ain, const fp16* __restrict__ Bin,
    float* __restrict__ outF32,
    const float* __restrict__ biasRow,
    const float* __restrict__ resid)
{
    extern __shared__ char smemraw[];
    int tid = threadIdx.x, wid = tid >> 5, lane = tid & 31;
    const int K = NPX;
    int bz = blockIdx.x >> 7;
    int rem = blockIdx.x & 127;
    int m0 = (rem >> 5) * 128;
    int n0 = (rem & 31) * 128;
    const fp16* A = Ain + (size_t)bz * NH;  int ldA = NPX;
    const fp16* B = Bin + (size_t)bz * NN;  int ldB = NPX;

    GEMM2_MAINLOOP()

    float* sp = (float*)smemraw;
    if (tid < 128) {
        const float* p = g_part + ((size_t)bz * NPX + n0 + tid) * 32;
        float s = 0.f;
        #pragma unroll
        for (int k = 0; k < 32; k++) s += p[k];
        sp[tid] = 1.0f / s;
    }
    __syncthreads();

    int r4 = lane >> 2;
    int c2 = lane & 3;
    float* of = outF32 + (size_t)bz * CCH * NPX;
    const float* rp = resid + (size_t)bz * CCH * NPX;

    #pragma unroll
    for (int mi = 0; mi < 4; mi++) {
        #pragma unroll
        for (int half = 0; half < 2; half++) {
            int m = m0 + wm * 64 + mi * 16 + half * 8 + r4;
            float brow = biasRow[m];
            #pragma unroll
            for (int ni = 0; ni < 4; ni++) {
                int n = n0 + wn * 32 + ni * 8 + c2 * 2;
                float v0 = acc[mi][ni][half * 2 + 0] * sp[n - n0]     + brow;
                float v1 = acc[mi][ni][half * 2 + 1] * sp[n + 1 - n0] + brow;
                size_t off = (size_t)m * NPX + n;
                float2 q = *(const float2*)(rp + off);
                v0 += q.x; v1 += q.y;
                *(float2*)(of + off) = make_float2(v0, v1);
            }
        }
    }
}

// ---------------- launch ----------------
extern "C" void kernel_launch(void* const* d_in, const int* in_sizes, int n_in,
                              void* d_out, int out_size) {
    const float* x     = (const float*)d_in[0];
    const float* gamma = (const float*)d_in[1];
    const float* beta  = (const float*)d_in[2];
    const float* wq    = (const float*)d_in[3];
    const float* bq    = (const float*)d_in[4];
    const float* wk    = (const float*)d_in[5];
    const float* bk    = (const float*)d_in[6];
    const float* wv    = (const float*)d_in[7];
    const float* bv    = (const float*)d_in[8];
    const float* wp    = (const float*)d_in[9];
    const float* bp    = (const float*)d_in[10];
    float* out = (float*)d_out;
    (void)bk;   // cancels in softmax (per-row constant)

    fp16 *ht, *Tt, *wv16, *E;
    cudaGetSymbolAddress((void**)&ht, g_ht);
    cudaGetSymbolAddress((void**)&Tt, g_T);
    cudaGetSymbolAddress((void**)&wv16, g_wv16);
    cudaGetSymbolAddress((void**)&E, g_E);

    const int SMEM_MID = 2 * T2STG;    // 73.7 KB
    const int SMEM_WPV = 3 * SSTG;     // 55 KB
    cudaFuncSetAttribute(gemm_twpv, cudaFuncAttributeMaxDynamicSharedMemorySize, SMEM_MID);
    cudaFuncSetAttribute(gemm_scores, cudaFuncAttributeMaxDynamicSharedMemorySize, SMEM_MID);
    cudaFuncSetAttribute(gemm_final, cudaFuncAttributeMaxDynamicSharedMemorySize, SMEM_MID);
    cudaFuncSetAttribute(small_gemms, cudaFuncAttributeMaxDynamicSharedMemorySize, SMEM_WPV);

    // fused prep (gn first)
    prep_all<<<1984, 256>>>(wq, wk, wv, wp, bq, bv, x, gamma, beta);

    // Wpv = wp@wv and G = wk^T@wq : 128 CTAs
    small_gemms<<<128, 256, SMEM_WPV>>>();

    // merged T + WpV : 512 mid-tile CTAs
    gemm_twpv<<<512, 256, SMEM_MID>>>(ht, Tt, wv16);

    // scores -> E = exp(scale * T@ht^T) + 32 partials/row
    const float scale = 1.0f / sqrtf((float)CCH);
    gemm_scores<<<dim3(32, 32, 2), 256, SMEM_MID>>>(Tt, ht, E, scale);

    // final
    gemm_final<<<256, 256, SMEM_MID>>>(wv16, E, out, bp, x);
}